// round 1
// baseline (speedup 1.0000x reference)
#include <cuda_runtime.h>
#include <cuda_bf16.h>
#include <math.h>

// Problem constants
#define BB 4
#define TT 2048
#define EE 256
#define HH 8
#define HD 32
#define FEE 4
#define LL 4
#define MROWS (BB*TT)          // 8192
#define EPS 1e-5f

// ---------------------------------------------------------------------------
// Scratch (device globals; no runtime allocation allowed)
// ---------------------------------------------------------------------------
__device__ float g_x   [MROWS * EE];          // activations (8 MB)
__device__ float g_qkv [MROWS * 3 * EE];      // qkv (24 MB)
__device__ float g_attn[MROWS * EE];          // attention output (8 MB)
__device__ float g_tmp [MROWS * EE];          // proj / ff2 result (8 MB)
__device__ float g_ffh [MROWS * FEE * EE];    // ff hidden (32 MB)

// ---------------------------------------------------------------------------
// Positional encoding: out = x + pe
// pe[t, i]      = sin(t * f_i)   for i < 128
// pe[t, 128+i]  = cos(t * f_i)
// f_i = 10000^(-2i/256)
// ---------------------------------------------------------------------------
__global__ void pe_kernel(const float* __restrict__ x, float* __restrict__ out) {
    int idx = blockIdx.x * blockDim.x + threadIdx.x;
    if (idx >= MROWS * EE) return;
    int e = idx & (EE - 1);
    int t = (idx / EE) & (TT - 1);
    int i = (e < 128) ? e : e - 128;
    // f = exp(-(2i/256) * ln(10000))
    float f = __expf(-((2.0f * (float)i) * (1.0f / (float)EE)) * 9.210340371976184f);
    float ang = (float)t * f;
    float pe = (e < 128) ? sinf(ang) : cosf(ang);
    out[idx] = x[idx] + pe;
}

// ---------------------------------------------------------------------------
// Tiled fp32 GEMM: C[M,N] = A[M,K] @ W[K,N] + bias[N]  (optional ReLU)
// BM=128, BN=64, BK=16, 256 threads, 8x4 per-thread micro-tile
// ---------------------------------------------------------------------------
#define BM 128
#define BN 64
#define BK 16
#define TM 8
#define TN 4

__global__ __launch_bounds__(256)
void gemm_bias_kernel(const float* __restrict__ A, const float* __restrict__ W,
                      const float* __restrict__ bias, float* __restrict__ C,
                      int M, int N, int K, int relu) {
    __shared__ float As[BK][BM + 4];   // transposed A tile (pad -> 16B-aligned reads)
    __shared__ float Ws[BK][BN];

    const int bm = blockIdx.y * BM;
    const int bn = blockIdx.x * BN;
    const int tx = threadIdx.x;        // 0..15
    const int ty = threadIdx.y;        // 0..15
    const int tid = ty * 16 + tx;

    const int a_col  = tid & (BK - 1); // 0..15
    const int a_row0 = tid >> 4;       // 0..15
    const int w_col  = tid & (BN - 1); // 0..63
    const int w_row0 = tid >> 6;       // 0..3

    float acc[TM][TN];
    #pragma unroll
    for (int i = 0; i < TM; i++)
        #pragma unroll
        for (int j = 0; j < TN; j++) acc[i][j] = 0.0f;

    for (int k0 = 0; k0 < K; k0 += BK) {
        #pragma unroll
        for (int i = 0; i < BM / 16; i++) {
            int r = a_row0 + i * 16;
            As[a_col][r] = A[(size_t)(bm + r) * K + k0 + a_col];
        }
        #pragma unroll
        for (int i = 0; i < BK / 4; i++) {
            int r = w_row0 + i * 4;
            Ws[r][w_col] = W[(size_t)(k0 + r) * N + bn + w_col];
        }
        __syncthreads();

        #pragma unroll
        for (int k = 0; k < BK; k++) {
            float a[TM], w[TN];
            #pragma unroll
            for (int i = 0; i < TM; i++) a[i] = As[k][ty * TM + i];
            #pragma unroll
            for (int j = 0; j < TN; j++) w[j] = Ws[k][tx * TN + j];
            #pragma unroll
            for (int i = 0; i < TM; i++)
                #pragma unroll
                for (int j = 0; j < TN; j++) acc[i][j] += a[i] * w[j];
        }
        __syncthreads();
    }

    #pragma unroll
    for (int i = 0; i < TM; i++) {
        int row = bm + ty * TM + i;
        #pragma unroll
        for (int j = 0; j < TN; j++) {
            int col = bn + tx * TN + j;
            float v = acc[i][j] + bias[col];
            if (relu) v = fmaxf(v, 0.0f);
            C[(size_t)row * N + col] = v;
        }
    }
}

// ---------------------------------------------------------------------------
// Flash-style attention (fp32, SIMT).
// qkv layout: [B, T, H, 3, HD] flattened -> (b*T+t)*768 + h*96 + s*32 + d
// out layout: [B, T, H, HD]              -> (b*T+t)*256 + h*32 + d
// One thread = one query row; K/V streamed through smem tiles of 128 keys.
// ---------------------------------------------------------------------------
#define KV_TILE 128

__global__ __launch_bounds__(128)
void flash_attn_kernel(const float* __restrict__ qkv, float* __restrict__ out) {
    __shared__ float Ks[KV_TILE][HD];
    __shared__ float Vs[KV_TILE][HD];

    const int qt = blockIdx.x & 15;        // 16 q-tiles of 128
    const int bh = blockIdx.x >> 4;        // 0..31
    const int h  = bh & (HH - 1);
    const int b  = bh / HH;
    const int tid = threadIdx.x;
    const int t  = qt * 128 + tid;

    const float scale = 0.17677669529663687f;  // 1/sqrt(32)
    const size_t row_base = (size_t)(b * TT + t) * (3 * EE) + h * (3 * HD);

    float q[HD];
    #pragma unroll
    for (int d = 0; d < HD; d++) q[d] = qkv[row_base + d] * scale;

    float o[HD];
    #pragma unroll
    for (int d = 0; d < HD; d++) o[d] = 0.0f;
    float m = -INFINITY, l = 0.0f;

    const size_t kv_base = (size_t)(b * TT) * (3 * EE) + h * (3 * HD);

    for (int kt = 0; kt < TT / KV_TILE; kt++) {
        __syncthreads();
        // cooperative load of K and V tiles (coalesced: d fastest)
        #pragma unroll
        for (int i = 0; i < (KV_TILE * HD) / 128; i++) {
            int e = tid + i * 128;
            int j = e >> 5;        // key within tile
            int d = e & 31;
            size_t src = kv_base + (size_t)(kt * KV_TILE + j) * (3 * EE);
            Ks[j][d] = qkv[src + HD + d];       // K slot (s=1)
            Vs[j][d] = qkv[src + 2 * HD + d];   // V slot (s=2)
        }
        __syncthreads();

        #pragma unroll 4
        for (int j = 0; j < KV_TILE; j++) {
            float s = 0.0f;
            #pragma unroll
            for (int d = 0; d < HD; d++) s += q[d] * Ks[j][d];
            float mnew = fmaxf(m, s);
            float corr = __expf(m - mnew);   // exp(-inf)=0 handles first iter
            float p    = __expf(s - mnew);
            l = l * corr + p;
            #pragma unroll
            for (int d = 0; d < HD; d++) o[d] = o[d] * corr + p * Vs[j][d];
            m = mnew;
        }
    }

    const float inv_l = 1.0f / l;
    const size_t out_base = (size_t)(b * TT + t) * EE + h * HD;
    #pragma unroll
    for (int d = 0; d < HD; d++) out[out_base + d] = o[d] * inv_l;
}

// ---------------------------------------------------------------------------
// Fused residual add + LayerNorm: out = LN(xin + res) * g + b
// One block per row, 256 threads (E=256).
// ---------------------------------------------------------------------------
__global__ __launch_bounds__(256)
void add_ln_kernel(const float* __restrict__ xin, const float* __restrict__ res,
                   const float* __restrict__ g, const float* __restrict__ beta,
                   float* __restrict__ out) {
    const int row = blockIdx.x;
    const int tid = threadIdx.x;
    const size_t idx = (size_t)row * EE + tid;

    float v = xin[idx] + res[idx];

    __shared__ float red[8];
    // mean
    float s = v;
    #pragma unroll
    for (int o = 16; o > 0; o >>= 1) s += __shfl_xor_sync(0xffffffffu, s, o);
    if ((tid & 31) == 0) red[tid >> 5] = s;
    __syncthreads();
    float tot = 0.0f;
    #pragma unroll
    for (int i = 0; i < 8; i++) tot += red[i];
    const float mu = tot * (1.0f / (float)EE);
    const float d = v - mu;
    __syncthreads();

    // variance
    float s2 = d * d;
    #pragma unroll
    for (int o = 16; o > 0; o >>= 1) s2 += __shfl_xor_sync(0xffffffffu, s2, o);
    if ((tid & 31) == 0) red[tid >> 5] = s2;
    __syncthreads();
    float tot2 = 0.0f;
    #pragma unroll
    for (int i = 0; i < 8; i++) tot2 += red[i];
    const float var = tot2 * (1.0f / (float)EE);

    out[idx] = d * rsqrtf(var + EPS) * g[tid] + beta[tid];
}

// ---------------------------------------------------------------------------
// kernel_launch
// ---------------------------------------------------------------------------
extern "C" void kernel_launch(void* const* d_in, const int* in_sizes, int n_in,
                              void* d_out, int out_size) {
    const float* x     = (const float*)d_in[0];
    const float* qkv_w = (const float*)d_in[1];
    const float* qkv_b = (const float*)d_in[2];
    const float* out_w = (const float*)d_in[3];
    const float* out_b = (const float*)d_in[4];
    const float* ff1_w = (const float*)d_in[5];
    const float* ff1_b = (const float*)d_in[6];
    const float* ff2_w = (const float*)d_in[7];
    const float* ff2_b = (const float*)d_in[8];
    const float* ln1_g = (const float*)d_in[9];
    const float* ln1_b = (const float*)d_in[10];
    const float* ln2_g = (const float*)d_in[11];
    const float* ln2_b = (const float*)d_in[12];
    float* outp = (float*)d_out;

    float *gx, *gqkv, *gattn, *gtmp, *gffh;
    cudaGetSymbolAddress((void**)&gx,   g_x);
    cudaGetSymbolAddress((void**)&gqkv, g_qkv);
    cudaGetSymbolAddress((void**)&gattn,g_attn);
    cudaGetSymbolAddress((void**)&gtmp, g_tmp);
    cudaGetSymbolAddress((void**)&gffh, g_ffh);

    // 1. x = x + PE
    pe_kernel<<<(MROWS * EE + 255) / 256, 256>>>(x, gx);

    const dim3 thr(16, 16);
    for (int i = 0; i < LL; i++) {
        // qkv = x @ qkv_w[i] + qkv_b[i]   (8192 x 768, K=256)
        gemm_bias_kernel<<<dim3((3 * EE) / BN, MROWS / BM), thr>>>(
            gx, qkv_w + (size_t)i * EE * 3 * EE, qkv_b + (size_t)i * 3 * EE,
            gqkv, MROWS, 3 * EE, EE, 0);

        // attention
        flash_attn_kernel<<<512, 128>>>(gqkv, gattn);

        // attn @ out_w[i] + out_b[i]      (8192 x 256, K=256)
        gemm_bias_kernel<<<dim3(EE / BN, MROWS / BM), thr>>>(
            gattn, out_w + (size_t)i * EE * EE, out_b + (size_t)i * EE,
            gtmp, MROWS, EE, EE, 0);

        // x = LN(x + proj)
        add_ln_kernel<<<MROWS, 256>>>(gx, gtmp,
            ln1_g + (size_t)i * EE, ln1_b + (size_t)i * EE, gx);

        // h = relu(x @ ff1_w + ff1_b)     (8192 x 1024, K=256)
        gemm_bias_kernel<<<dim3((FEE * EE) / BN, MROWS / BM), thr>>>(
            gx, ff1_w + (size_t)i * EE * FEE * EE, ff1_b + (size_t)i * FEE * EE,
            gffh, MROWS, FEE * EE, EE, 1);

        // ff = h @ ff2_w + ff2_b          (8192 x 256, K=1024)
        gemm_bias_kernel<<<dim3(EE / BN, MROWS / BM), thr>>>(
            gffh, ff2_w + (size_t)i * FEE * EE * EE, ff2_b + (size_t)i * EE,
            gtmp, MROWS, EE, FEE * EE, 0);

        // x = LN(x + ff)   (last layer writes straight to d_out)
        float* dst = (i == LL - 1) ? outp : gx;
        add_ln_kernel<<<MROWS, 256>>>(gx, gtmp,
            ln2_g + (size_t)i * EE, ln2_b + (size_t)i * EE, dst);
    }
}

// round 4
// speedup vs baseline: 2.1841x; 2.1841x over previous
#include <cuda_runtime.h>
#include <cuda_bf16.h>
#include <math.h>
#include <cstdint>

// Problem constants
#define BB 4
#define TT 2048
#define EE 256
#define HH 8
#define HD 32
#define FEE 4
#define LL 4
#define MROWS (BB*TT)          // 8192
#define EPS 1e-5f

// ---------------------------------------------------------------------------
// Scratch (device globals; no runtime allocation allowed)
// ---------------------------------------------------------------------------
__device__ float g_x   [MROWS * EE];
__device__ float g_qkv [MROWS * 3 * EE];
__device__ float g_attn[MROWS * EE];
__device__ float g_tmp [MROWS * EE];
__device__ float g_ffh [MROWS * FEE * EE];
// transposed weights [N, K] row-major, per layer (tf32-rounded)
__device__ float g_qkvw_t[LL * 3 * EE * EE];
__device__ float g_outw_t[LL * EE * EE];
__device__ float g_ff1w_t[LL * FEE * EE * EE];
__device__ float g_ff2w_t[LL * FEE * EE * EE];

// ---------------------------------------------------------------------------
// PTX helpers (sm_80-era only; target is plain sm_103 — no tcgen05!)
// ---------------------------------------------------------------------------
__device__ __forceinline__ uint32_t smem_u32(const void* p) {
    uint32_t a;
    asm("{ .reg .u64 t; cvta.to.shared.u64 t, %1; cvt.u32.u64 %0, t; }" : "=r"(a) : "l"(p));
    return a;
}

__device__ __forceinline__ float tf32_rn(float x) {
    uint32_t u;
    asm("cvt.rna.tf32.f32 %0, %1;" : "=r"(u) : "f"(x));
    return __uint_as_float(u);
}

#define CP_ASYNC16(dst, src) \
    asm volatile("cp.async.cg.shared.global [%0], [%1], 16;\n" :: "r"(dst), "l"(src))
#define CP_COMMIT() asm volatile("cp.async.commit_group;\n" ::)
#define CP_WAIT1() asm volatile("cp.async.wait_group 1;\n" ::)
#define CP_WAIT0() asm volatile("cp.async.wait_group 0;\n" ::)

#define LDSM_X4(r, addr) \
    asm volatile("ldmatrix.sync.aligned.m8n8.x4.shared.b16 {%0,%1,%2,%3}, [%4];" \
        : "=r"((r)[0]), "=r"((r)[1]), "=r"((r)[2]), "=r"((r)[3]) : "r"(addr))

__device__ __forceinline__ void mma_tf32(float c[4], const uint32_t a[4], const uint32_t b[2]) {
    asm volatile("mma.sync.aligned.m16n8k8.row.col.f32.tf32.tf32.f32 "
        "{%0,%1,%2,%3}, {%4,%5,%6,%7}, {%8,%9}, {%0,%1,%2,%3};"
        : "+f"(c[0]), "+f"(c[1]), "+f"(c[2]), "+f"(c[3])
        : "r"(a[0]), "r"(a[1]), "r"(a[2]), "r"(a[3]), "r"(b[0]), "r"(b[1]));
}

// ---------------------------------------------------------------------------
// Positional encoding
// ---------------------------------------------------------------------------
__global__ void pe_kernel(const float* __restrict__ x, float* __restrict__ out) {
    int idx = blockIdx.x * blockDim.x + threadIdx.x;
    if (idx >= MROWS * EE) return;
    int e = idx & (EE - 1);
    int t = (idx / EE) & (TT - 1);
    int i = (e < 128) ? e : e - 128;
    float f = __expf(-((2.0f * (float)i) * (1.0f / (float)EE)) * 9.210340371976184f);
    float ang = (float)t * f;
    float pe = (e < 128) ? sinf(ang) : cosf(ang);
    out[idx] = x[idx] + pe;
}

// ---------------------------------------------------------------------------
// Weight transpose + tf32 round-to-nearest: in [l][K][N] -> out [l][N][K]
// ---------------------------------------------------------------------------
__global__ void transpose_kernel(const float* __restrict__ in, float* __restrict__ out,
                                 int K, int N) {
    __shared__ float tile[32][33];
    const size_t plane = (size_t)K * N;
    const float* ip = in + blockIdx.z * plane;
    float* op = out + blockIdx.z * plane;
    int n0 = blockIdx.x * 32, k0 = blockIdx.y * 32;
    int tx = threadIdx.x, ty = threadIdx.y;
    #pragma unroll
    for (int i = 0; i < 32; i += 8)
        tile[ty + i][tx] = ip[(size_t)(k0 + ty + i) * N + n0 + tx];
    __syncthreads();
    #pragma unroll
    for (int i = 0; i < 32; i += 8)
        op[(size_t)(n0 + ty + i) * K + k0 + tx] = tf32_rn(tile[tx][ty + i]);
}

// ---------------------------------------------------------------------------
// tf32 mma.sync GEMM: C[M,N] = A[M,K] @ Bt[N,K]^T + bias  (optional ReLU)
// Block tile 128x128, BK=32, 8 warps (2m x 4n), warp tile m64 n32.
// Double-buffered cp.async with SW128 swizzle; ldmatrix fragment loads.
// ---------------------------------------------------------------------------
#define SA0 0
#define SA1 16384
#define SB0 32768
#define SB1 49152
#define GSMEM_TOTAL 65536

__device__ __forceinline__ void gemm_load_stage(uint32_t sbase, const float* A, const float* Bt,
                                                int K, int bm, int bn, int kt, int tid) {
    uint32_t abuf = sbase + ((kt & 1) ? SA1 : SA0);
    uint32_t bbuf = sbase + ((kt & 1) ? SB1 : SB0);
    const float* ap = A + (size_t)bm * K + kt * 32;
    const float* bp = Bt + (size_t)bn * K + kt * 32;
    #pragma unroll
    for (int i = 0; i < 4; i++) {
        int f = tid + i * 256;           // 0..1023 16B chunks
        int r = f >> 3;                  // row 0..127
        int cB = (f & 7) * 16;           // byte col 0..112
        uint32_t off = (uint32_t)(r * 128 + cB);
        uint32_t sw = off ^ ((off >> 3) & 0x70);
        CP_ASYNC16(abuf + sw, ap + (size_t)r * K + (cB >> 2));
        CP_ASYNC16(bbuf + sw, bp + (size_t)r * K + (cB >> 2));
    }
    CP_COMMIT();
}

__global__ __launch_bounds__(256)
void gemm_tc_kernel(const float* __restrict__ A, const float* __restrict__ Bt,
                    const float* __restrict__ bias, float* __restrict__ C,
                    int N, int K, int relu) {
    extern __shared__ char smem[];
    uint32_t sbase = smem_u32(smem);
    const int tid = threadIdx.x;
    const int wid = tid >> 5;
    const int lane = tid & 31;
    const int warpM = wid & 1;          // 2 warps over M
    const int warpN = wid >> 1;         // 4 warps over N
    const int bn = blockIdx.x * 128;
    const int bm = blockIdx.y * 128;

    float acc[4][4][4];
    #pragma unroll
    for (int mt = 0; mt < 4; mt++)
        #pragma unroll
        for (int nt = 0; nt < 4; nt++)
            #pragma unroll
            for (int r = 0; r < 4; r++) acc[mt][nt][r] = 0.0f;

    // ldmatrix address precompute (swizzle = XOR bits[6:4] with row bits[2:0])
    const uint32_t mask = (uint32_t)(lane & 7) << 4;
    uint32_t arowb[4];
    #pragma unroll
    for (int mt = 0; mt < 4; mt++)
        arowb[mt] = (uint32_t)(warpM * 64 + (lane & 15) + mt * 16) * 128;
    const uint32_t achunk = (uint32_t)(lane >> 4) * 16;
    uint32_t browb[2];
    #pragma unroll
    for (int nh = 0; nh < 2; nh++)
        browb[nh] = (uint32_t)(warpN * 32 + nh * 16 + (lane & 7) + ((lane >> 4) << 3)) * 128;
    const uint32_t bchunk = (uint32_t)((lane >> 3) & 1) * 16;

    const int nk = K / 32;
    gemm_load_stage(sbase, A, Bt, K, bm, bn, 0, tid);
    gemm_load_stage(sbase, A, Bt, K, bm, bn, 1, tid);

    for (int kt = 0; kt < nk; kt++) {
        if (kt + 2 <= nk) { CP_WAIT1(); } else { CP_WAIT0(); }
        __syncthreads();

        const uint32_t ab = sbase + ((kt & 1) ? SA1 : SA0);
        const uint32_t bb = sbase + ((kt & 1) ? SB1 : SB0);

        #pragma unroll
        for (int ks = 0; ks < 4; ks++) {
            const uint32_t aco = ((uint32_t)(ks * 32) + achunk) ^ mask;
            const uint32_t bco = ((uint32_t)(ks * 32) + bchunk) ^ mask;

            uint32_t afr[4][4], bfr[2][4];
            #pragma unroll
            for (int mt = 0; mt < 4; mt++) LDSM_X4(afr[mt], ab + arowb[mt] + aco);
            #pragma unroll
            for (int nh = 0; nh < 2; nh++) LDSM_X4(bfr[nh], bb + browb[nh] + bco);

            // RN-round activations to tf32 (weights already rounded at transpose)
            #pragma unroll
            for (int mt = 0; mt < 4; mt++)
                #pragma unroll
                for (int r = 0; r < 4; r++)
                    afr[mt][r] = __float_as_uint(tf32_rn(__uint_as_float(afr[mt][r])));

            #pragma unroll
            for (int mt = 0; mt < 4; mt++)
                #pragma unroll
                for (int nt = 0; nt < 4; nt++)
                    mma_tf32(acc[mt][nt], afr[mt], &bfr[nt >> 1][(nt & 1) * 2]);
        }

        __syncthreads();
        if (kt + 2 < nk) gemm_load_stage(sbase, A, Bt, K, bm, bn, kt + 2, tid);
    }

    // Epilogue: bias (+ReLU), direct float2 stores
    #pragma unroll
    for (int mt = 0; mt < 4; mt++) {
        const int row0 = bm + warpM * 64 + mt * 16 + (lane >> 2);
        #pragma unroll
        for (int nt = 0; nt < 4; nt++) {
            const int col = bn + warpN * 32 + nt * 8 + (lane & 3) * 2;
            const float2 bi = *(const float2*)&bias[col];
            float v0 = acc[mt][nt][0] + bi.x;
            float v1 = acc[mt][nt][1] + bi.y;
            float v2 = acc[mt][nt][2] + bi.x;
            float v3 = acc[mt][nt][3] + bi.y;
            if (relu) {
                v0 = fmaxf(v0, 0.0f); v1 = fmaxf(v1, 0.0f);
                v2 = fmaxf(v2, 0.0f); v3 = fmaxf(v3, 0.0f);
            }
            float2 p0; p0.x = v0; p0.y = v1;
            float2 p1; p1.x = v2; p1.y = v3;
            *(float2*)&C[(size_t)row0 * N + col] = p0;
            *(float2*)&C[(size_t)(row0 + 8) * N + col] = p1;
        }
    }
}

// ---------------------------------------------------------------------------
// Flash attention (fp32 SIMT, chunked softmax, vectorized smem)
// qkv layout: [B,T,H,3,HD] -> (b*T+t)*768 + h*96 + s*32 + d
// ---------------------------------------------------------------------------
#define KV_TILE 128

__global__ __launch_bounds__(128)
void flash_attn_kernel(const float* __restrict__ qkv, float* __restrict__ out) {
    __shared__ float Ks[KV_TILE][HD];
    __shared__ float Vs[KV_TILE][HD];

    const int qt = blockIdx.x & 15;
    const int bh = blockIdx.x >> 4;
    const int h  = bh & (HH - 1);
    const int b  = bh / HH;
    const int tid = threadIdx.x;
    const int t  = qt * 128 + tid;

    const float scale = 0.17677669529663687f;
    const size_t row_base = (size_t)(b * TT + t) * (3 * EE) + h * (3 * HD);

    float q[HD];
    {
        const float4* q4 = (const float4*)(qkv + row_base);
        #pragma unroll
        for (int d4 = 0; d4 < 8; d4++) {
            float4 v = q4[d4];
            q[4*d4+0] = v.x * scale; q[4*d4+1] = v.y * scale;
            q[4*d4+2] = v.z * scale; q[4*d4+3] = v.w * scale;
        }
    }

    float o[HD];
    #pragma unroll
    for (int d = 0; d < HD; d++) o[d] = 0.0f;
    float m = -INFINITY, l = 0.0f;

    const size_t kv_base = (size_t)(b * TT) * (3 * EE) + h * (3 * HD);

    for (int kt = 0; kt < TT / KV_TILE; kt++) {
        __syncthreads();
        #pragma unroll
        for (int i = 0; i < 8; i++) {
            int e = tid + i * 128;
            int j = e >> 3;
            int d4 = e & 7;
            const float4* src = (const float4*)(qkv + kv_base + (size_t)(kt * KV_TILE + j) * (3 * EE));
            ((float4*)Ks[j])[d4] = src[8 + d4];
            ((float4*)Vs[j])[d4] = src[16 + d4];
        }
        __syncthreads();

        for (int jc = 0; jc < KV_TILE / 8; jc++) {
            float s[8];
            #pragma unroll
            for (int jj = 0; jj < 8; jj++) {
                const float4* k4 = (const float4*)(&Ks[jc * 8 + jj][0]);
                float a0 = 0.f, a1 = 0.f, a2 = 0.f, a3 = 0.f;
                #pragma unroll
                for (int d4 = 0; d4 < 8; d4++) {
                    float4 kv = k4[d4];
                    a0 += q[4*d4+0] * kv.x; a1 += q[4*d4+1] * kv.y;
                    a2 += q[4*d4+2] * kv.z; a3 += q[4*d4+3] * kv.w;
                }
                s[jj] = (a0 + a1) + (a2 + a3);
            }
            float cm = s[0];
            #pragma unroll
            for (int jj = 1; jj < 8; jj++) cm = fmaxf(cm, s[jj]);
            float mnew = fmaxf(m, cm);
            float corr = __expf(m - mnew);
            m = mnew;
            l *= corr;
            #pragma unroll
            for (int d = 0; d < HD; d++) o[d] *= corr;
            #pragma unroll
            for (int jj = 0; jj < 8; jj++) {
                float p = __expf(s[jj] - mnew);
                l += p;
                const float4* v4 = (const float4*)(&Vs[jc * 8 + jj][0]);
                #pragma unroll
                for (int d4 = 0; d4 < 8; d4++) {
                    float4 vv = v4[d4];
                    o[4*d4+0] += p * vv.x; o[4*d4+1] += p * vv.y;
                    o[4*d4+2] += p * vv.z; o[4*d4+3] += p * vv.w;
                }
            }
        }
    }

    const float inv_l = 1.0f / l;
    float4* o4 = (float4*)(out + (size_t)(b * TT + t) * EE + h * HD);
    #pragma unroll
    for (int d4 = 0; d4 < 8; d4++) {
        float4 v;
        v.x = o[4*d4+0] * inv_l; v.y = o[4*d4+1] * inv_l;
        v.z = o[4*d4+2] * inv_l; v.w = o[4*d4+3] * inv_l;
        o4[d4] = v;
    }
}

// ---------------------------------------------------------------------------
// Fused residual add + LayerNorm
// ---------------------------------------------------------------------------
__global__ __launch_bounds__(256)
void add_ln_kernel(const float* __restrict__ xin, const float* __restrict__ res,
                   const float* __restrict__ g, const float* __restrict__ beta,
                   float* __restrict__ out) {
    const int row = blockIdx.x;
    const int tid = threadIdx.x;
    const size_t idx = (size_t)row * EE + tid;

    float v = xin[idx] + res[idx];

    __shared__ float red[8];
    float s = v;
    #pragma unroll
    for (int o = 16; o > 0; o >>= 1) s += __shfl_xor_sync(0xffffffffu, s, o);
    if ((tid & 31) == 0) red[tid >> 5] = s;
    __syncthreads();
    float tot = 0.0f;
    #pragma unroll
    for (int i = 0; i < 8; i++) tot += red[i];
    const float mu = tot * (1.0f / (float)EE);
    const float d = v - mu;
    __syncthreads();

    float s2 = d * d;
    #pragma unroll
    for (int o = 16; o > 0; o >>= 1) s2 += __shfl_xor_sync(0xffffffffu, s2, o);
    if ((tid & 31) == 0) red[tid >> 5] = s2;
    __syncthreads();
    float tot2 = 0.0f;
    #pragma unroll
    for (int i = 0; i < 8; i++) tot2 += red[i];
    const float var = tot2 * (1.0f / (float)EE);

    out[idx] = d * rsqrtf(var + EPS) * g[tid] + beta[tid];
}

// ---------------------------------------------------------------------------
// kernel_launch
// ---------------------------------------------------------------------------
extern "C" void kernel_launch(void* const* d_in, const int* in_sizes, int n_in,
                              void* d_out, int out_size) {
    const float* x     = (const float*)d_in[0];
    const float* qkv_w = (const float*)d_in[1];
    const float* qkv_b = (const float*)d_in[2];
    const float* out_w = (const float*)d_in[3];
    const float* out_b = (const float*)d_in[4];
    const float* ff1_w = (const float*)d_in[5];
    const float* ff1_b = (const float*)d_in[6];
    const float* ff2_w = (const float*)d_in[7];
    const float* ff2_b = (const float*)d_in[8];
    const float* ln1_g = (const float*)d_in[9];
    const float* ln1_b = (const float*)d_in[10];
    const float* ln2_g = (const float*)d_in[11];
    const float* ln2_b = (const float*)d_in[12];
    float* outp = (float*)d_out;

    float *gx, *gqkv, *gattn, *gtmp, *gffh, *wq, *wo, *w1, *w2;
    cudaGetSymbolAddress((void**)&gx,   g_x);
    cudaGetSymbolAddress((void**)&gqkv, g_qkv);
    cudaGetSymbolAddress((void**)&gattn,g_attn);
    cudaGetSymbolAddress((void**)&gtmp, g_tmp);
    cudaGetSymbolAddress((void**)&gffh, g_ffh);
    cudaGetSymbolAddress((void**)&wq,   g_qkvw_t);
    cudaGetSymbolAddress((void**)&wo,   g_outw_t);
    cudaGetSymbolAddress((void**)&w1,   g_ff1w_t);
    cudaGetSymbolAddress((void**)&w2,   g_ff2w_t);

    cudaFuncSetAttribute(gemm_tc_kernel, cudaFuncAttributeMaxDynamicSharedMemorySize, GSMEM_TOTAL);

    const dim3 tthr(32, 8);
    transpose_kernel<<<dim3(24, 8, LL), tthr>>>(qkv_w, wq, EE, 3 * EE);
    transpose_kernel<<<dim3(8, 8, LL), tthr>>>(out_w, wo, EE, EE);
    transpose_kernel<<<dim3(32, 8, LL), tthr>>>(ff1_w, w1, EE, FEE * EE);
    transpose_kernel<<<dim3(8, 32, LL), tthr>>>(ff2_w, w2, FEE * EE, EE);

    pe_kernel<<<(MROWS * EE + 255) / 256, 256>>>(x, gx);

    for (int i = 0; i < LL; i++) {
        // qkv = x @ qkv_w + b    (8192 x 768, K=256)
        gemm_tc_kernel<<<dim3(6, 64), 256, GSMEM_TOTAL>>>(
            gx, wq + (size_t)i * 3 * EE * EE, qkv_b + (size_t)i * 3 * EE,
            gqkv, 3 * EE, EE, 0);

        flash_attn_kernel<<<512, 128>>>(gqkv, gattn);

        // proj = attn @ out_w + b  (8192 x 256, K=256)
        gemm_tc_kernel<<<dim3(2, 64), 256, GSMEM_TOTAL>>>(
            gattn, wo + (size_t)i * EE * EE, out_b + (size_t)i * EE,
            gtmp, EE, EE, 0);

        add_ln_kernel<<<MROWS, 256>>>(gx, gtmp,
            ln1_g + (size_t)i * EE, ln1_b + (size_t)i * EE, gx);

        // h = relu(x @ ff1_w + b)  (8192 x 1024, K=256)
        gemm_tc_kernel<<<dim3(8, 64), 256, GSMEM_TOTAL>>>(
            gx, w1 + (size_t)i * FEE * EE * EE, ff1_b + (size_t)i * FEE * EE,
            gffh, FEE * EE, EE, 1);

        // ff = h @ ff2_w + b       (8192 x 256, K=1024)
        gemm_tc_kernel<<<dim3(2, 64), 256, GSMEM_TOTAL>>>(
            gffh, w2 + (size_t)i * FEE * EE * EE, ff2_b + (size_t)i * EE,
            gtmp, EE, FEE * EE, 0);

        float* dst = (i == LL - 1) ? outp : gx;
        add_ln_kernel<<<MROWS, 256>>>(gx, gtmp,
            ln2_g + (size_t)i * EE, ln2_b + (size_t)i * EE, dst);
    }
}

// round 5
// speedup vs baseline: 5.2247x; 2.3922x over previous
#include <cuda_runtime.h>
#include <cuda_bf16.h>
#include <math.h>
#include <cstdint>

// Problem constants
#define BB 4
#define TT 2048
#define EE 256
#define HH 8
#define HD 32
#define FEE 4
#define LL 4
#define MROWS (BB*TT)          // 8192
#define EPS 1e-5f

// ---------------------------------------------------------------------------
// Scratch (device globals; no runtime allocation allowed)
// ---------------------------------------------------------------------------
__device__ float g_x   [MROWS * EE];
__device__ float g_qkv [MROWS * 3 * EE];
__device__ float g_attn[MROWS * EE];
__device__ float g_tmp [MROWS * EE];
__device__ float g_ffh [MROWS * FEE * EE];
// transposed weights [N, K] row-major, per layer (tf32-rounded)
__device__ float g_qkvw_t[LL * 3 * EE * EE];
__device__ float g_outw_t[LL * EE * EE];
__device__ float g_ff1w_t[LL * FEE * EE * EE];
__device__ float g_ff2w_t[LL * FEE * EE * EE];

// ---------------------------------------------------------------------------
// PTX helpers (sm_80-era only; target is plain sm_103 — no tcgen05!)
// ---------------------------------------------------------------------------
__device__ __forceinline__ uint32_t smem_u32(const void* p) {
    uint32_t a;
    asm("{ .reg .u64 t; cvta.to.shared.u64 t, %1; cvt.u32.u64 %0, t; }" : "=r"(a) : "l"(p));
    return a;
}

__device__ __forceinline__ float tf32_rn(float x) {
    uint32_t u;
    asm("cvt.rna.tf32.f32 %0, %1;" : "=r"(u) : "f"(x));
    return __uint_as_float(u);
}

#define CP_ASYNC16(dst, src) \
    asm volatile("cp.async.cg.shared.global [%0], [%1], 16;\n" :: "r"(dst), "l"(src))
#define CP_COMMIT() asm volatile("cp.async.commit_group;\n" ::)
#define CP_WAIT1() asm volatile("cp.async.wait_group 1;\n" ::)
#define CP_WAIT0() asm volatile("cp.async.wait_group 0;\n" ::)

#define LDSM_X4(r, addr) \
    asm volatile("ldmatrix.sync.aligned.m8n8.x4.shared.b16 {%0,%1,%2,%3}, [%4];" \
        : "=r"((r)[0]), "=r"((r)[1]), "=r"((r)[2]), "=r"((r)[3]) : "r"(addr))

__device__ __forceinline__ void mma_tf32(float c[4], const uint32_t a[4], const uint32_t b[2]) {
    asm volatile("mma.sync.aligned.m16n8k8.row.col.f32.tf32.tf32.f32 "
        "{%0,%1,%2,%3}, {%4,%5,%6,%7}, {%8,%9}, {%0,%1,%2,%3};"
        : "+f"(c[0]), "+f"(c[1]), "+f"(c[2]), "+f"(c[3])
        : "r"(a[0]), "r"(a[1]), "r"(a[2]), "r"(a[3]), "r"(b[0]), "r"(b[1]));
}

// ---------------------------------------------------------------------------
// Positional encoding
// ---------------------------------------------------------------------------
__global__ void pe_kernel(const float* __restrict__ x, float* __restrict__ out) {
    int idx = blockIdx.x * blockDim.x + threadIdx.x;
    if (idx >= MROWS * EE) return;
    int e = idx & (EE - 1);
    int t = (idx / EE) & (TT - 1);
    int i = (e < 128) ? e : e - 128;
    float f = __expf(-((2.0f * (float)i) * (1.0f / (float)EE)) * 9.210340371976184f);
    float ang = (float)t * f;
    float pe = (e < 128) ? sinf(ang) : cosf(ang);
    out[idx] = x[idx] + pe;
}

// ---------------------------------------------------------------------------
// Weight transpose + tf32 round-to-nearest: in [l][K][N] -> out [l][N][K]
// ---------------------------------------------------------------------------
__global__ void transpose_kernel(const float* __restrict__ in, float* __restrict__ out,
                                 int K, int N) {
    __shared__ float tile[32][33];
    const size_t plane = (size_t)K * N;
    const float* ip = in + blockIdx.z * plane;
    float* op = out + blockIdx.z * plane;
    int n0 = blockIdx.x * 32, k0 = blockIdx.y * 32;
    int tx = threadIdx.x, ty = threadIdx.y;
    #pragma unroll
    for (int i = 0; i < 32; i += 8)
        tile[ty + i][tx] = ip[(size_t)(k0 + ty + i) * N + n0 + tx];
    __syncthreads();
    #pragma unroll
    for (int i = 0; i < 32; i += 8)
        op[(size_t)(n0 + ty + i) * K + k0 + tx] = tf32_rn(tile[tx][ty + i]);
}

// ---------------------------------------------------------------------------
// tf32 mma.sync GEMM: C[M,N] = A[M,K] @ Bt[N,K]^T + bias  (optional ReLU)
// Block tile 128x128, BK=32, 8 warps (2m x 4n), warp tile m64 n32.
// ---------------------------------------------------------------------------
#define SA0 0
#define SA1 16384
#define SB0 32768
#define SB1 49152
#define GSMEM_TOTAL 65536

__device__ __forceinline__ void gemm_load_stage(uint32_t sbase, const float* A, const float* Bt,
                                                int K, int bm, int bn, int kt, int tid) {
    uint32_t abuf = sbase + ((kt & 1) ? SA1 : SA0);
    uint32_t bbuf = sbase + ((kt & 1) ? SB1 : SB0);
    const float* ap = A + (size_t)bm * K + kt * 32;
    const float* bp = Bt + (size_t)bn * K + kt * 32;
    #pragma unroll
    for (int i = 0; i < 4; i++) {
        int f = tid + i * 256;
        int r = f >> 3;
        int cB = (f & 7) * 16;
        uint32_t off = (uint32_t)(r * 128 + cB);
        uint32_t sw = off ^ ((off >> 3) & 0x70);
        CP_ASYNC16(abuf + sw, ap + (size_t)r * K + (cB >> 2));
        CP_ASYNC16(bbuf + sw, bp + (size_t)r * K + (cB >> 2));
    }
    CP_COMMIT();
}

__global__ __launch_bounds__(256)
void gemm_tc_kernel(const float* __restrict__ A, const float* __restrict__ Bt,
                    const float* __restrict__ bias, float* __restrict__ C,
                    int N, int K, int relu) {
    extern __shared__ char smem[];
    uint32_t sbase = smem_u32(smem);
    const int tid = threadIdx.x;
    const int wid = tid >> 5;
    const int lane = tid & 31;
    const int warpM = wid & 1;
    const int warpN = wid >> 1;
    const int bn = blockIdx.x * 128;
    const int bm = blockIdx.y * 128;

    float acc[4][4][4];
    #pragma unroll
    for (int mt = 0; mt < 4; mt++)
        #pragma unroll
        for (int nt = 0; nt < 4; nt++)
            #pragma unroll
            for (int r = 0; r < 4; r++) acc[mt][nt][r] = 0.0f;

    const uint32_t mask = (uint32_t)(lane & 7) << 4;
    uint32_t arowb[4];
    #pragma unroll
    for (int mt = 0; mt < 4; mt++)
        arowb[mt] = (uint32_t)(warpM * 64 + (lane & 15) + mt * 16) * 128;
    const uint32_t achunk = (uint32_t)(lane >> 4) * 16;
    uint32_t browb[2];
    #pragma unroll
    for (int nh = 0; nh < 2; nh++)
        browb[nh] = (uint32_t)(warpN * 32 + nh * 16 + (lane & 7) + ((lane >> 4) << 3)) * 128;
    const uint32_t bchunk = (uint32_t)((lane >> 3) & 1) * 16;

    const int nk = K / 32;
    gemm_load_stage(sbase, A, Bt, K, bm, bn, 0, tid);
    gemm_load_stage(sbase, A, Bt, K, bm, bn, 1, tid);

    for (int kt = 0; kt < nk; kt++) {
        if (kt + 2 <= nk) { CP_WAIT1(); } else { CP_WAIT0(); }
        __syncthreads();

        const uint32_t ab = sbase + ((kt & 1) ? SA1 : SA0);
        const uint32_t bb = sbase + ((kt & 1) ? SB1 : SB0);

        #pragma unroll
        for (int ks = 0; ks < 4; ks++) {
            const uint32_t aco = ((uint32_t)(ks * 32) + achunk) ^ mask;
            const uint32_t bco = ((uint32_t)(ks * 32) + bchunk) ^ mask;

            uint32_t afr[4][4], bfr[2][4];
            #pragma unroll
            for (int mt = 0; mt < 4; mt++) LDSM_X4(afr[mt], ab + arowb[mt] + aco);
            #pragma unroll
            for (int nh = 0; nh < 2; nh++) LDSM_X4(bfr[nh], bb + browb[nh] + bco);

            #pragma unroll
            for (int mt = 0; mt < 4; mt++)
                #pragma unroll
                for (int r = 0; r < 4; r++)
                    afr[mt][r] = __float_as_uint(tf32_rn(__uint_as_float(afr[mt][r])));

            #pragma unroll
            for (int mt = 0; mt < 4; mt++)
                #pragma unroll
                for (int nt = 0; nt < 4; nt++)
                    mma_tf32(acc[mt][nt], afr[mt], &bfr[nt >> 1][(nt & 1) * 2]);
        }

        __syncthreads();
        if (kt + 2 < nk) gemm_load_stage(sbase, A, Bt, K, bm, bn, kt + 2, tid);
    }

    #pragma unroll
    for (int mt = 0; mt < 4; mt++) {
        const int row0 = bm + warpM * 64 + mt * 16 + (lane >> 2);
        #pragma unroll
        for (int nt = 0; nt < 4; nt++) {
            const int col = bn + warpN * 32 + nt * 8 + (lane & 3) * 2;
            const float2 bi = *(const float2*)&bias[col];
            float v0 = acc[mt][nt][0] + bi.x;
            float v1 = acc[mt][nt][1] + bi.y;
            float v2 = acc[mt][nt][2] + bi.x;
            float v3 = acc[mt][nt][3] + bi.y;
            if (relu) {
                v0 = fmaxf(v0, 0.0f); v1 = fmaxf(v1, 0.0f);
                v2 = fmaxf(v2, 0.0f); v3 = fmaxf(v3, 0.0f);
            }
            float2 p0; p0.x = v0; p0.y = v1;
            float2 p1; p1.x = v2; p1.y = v3;
            *(float2*)&C[(size_t)row0 * N + col] = p0;
            *(float2*)&C[(size_t)(row0 + 8) * N + col] = p1;
        }
    }
}

// ---------------------------------------------------------------------------
// Tensor-core flash attention (tf32 mma.sync).
// Block = (b,h) x 64-query tile; 4 warps x 16 rows. KV tiles of 64 keys.
// qkv layout: [B,T,H,3,HD] -> (b*T+t)*768 + h*96 + s*32 + d
// ---------------------------------------------------------------------------
#define VPAD 68

__global__ __launch_bounds__(128)
void attn_tc_kernel(const float* __restrict__ qkv, float* __restrict__ out) {
    __shared__ float Ks[64 * 32];            // SW128-swizzled, 128B rows
    __shared__ float Vt[32][VPAD];           // V^T [d][key], padded
    __shared__ float Pb[4][16 * VPAD];       // per-warp P [16][VPAD]

    const int tid = threadIdx.x;
    const int wid = tid >> 5;
    const int lane = tid & 31;
    const int qt = blockIdx.x;               // 0..31
    const int bh = blockIdx.y;               // 0..31
    const int h = bh & (HH - 1);
    const int b = bh >> 3;

    const uint32_t kbase = smem_u32(Ks);
    const float scale = 0.17677669529663687f;   // 1/sqrt(32)

    // --- Q fragments (A, m16k8 x 4 ksteps), pre-scaled + tf32 RN rounded ---
    uint32_t qfr[4][4];
    {
        const int r_lo = qt * 64 + wid * 16 + (lane >> 2);
        const size_t base_lo = (size_t)(b * TT + r_lo) * 768 + h * 96;
        const size_t base_hi = base_lo + 8 * 768;
        #pragma unroll
        for (int ks = 0; ks < 4; ks++) {
            int c0 = ks * 8 + (lane & 3);
            qfr[ks][0] = __float_as_uint(tf32_rn(qkv[base_lo + c0] * scale));
            qfr[ks][1] = __float_as_uint(tf32_rn(qkv[base_hi + c0] * scale));
            qfr[ks][2] = __float_as_uint(tf32_rn(qkv[base_lo + c0 + 4] * scale));
            qfr[ks][3] = __float_as_uint(tf32_rn(qkv[base_hi + c0 + 4] * scale));
        }
    }

    float ofr[4][4];
    #pragma unroll
    for (int nd = 0; nd < 4; nd++)
        #pragma unroll
        for (int r = 0; r < 4; r++) ofr[nd][r] = 0.0f;
    float m_lo = -INFINITY, m_hi = -INFINITY, l_lo = 0.0f, l_hi = 0.0f;

    // ldmatrix addressing for K tile (B fragments)
    const uint32_t mask = (uint32_t)(lane & 7) << 4;
    const uint32_t krow = (uint32_t)((lane & 7) + ((lane >> 4) << 3)) * 128;
    const uint32_t kchunk = (uint32_t)((lane >> 3) & 1) * 16;

    float* Pw = &Pb[wid][0];
    const uint32_t* Pwu = (const uint32_t*)Pw;
    const uint32_t* Vtu = (const uint32_t*)&Vt[0][0];

    const size_t kv_stride = 768;
    const size_t kv_base0 = (size_t)(b * TT) * 768 + h * 96;

    for (int kt = 0; kt < TT / 64; kt++) {
        __syncthreads();
        // cooperative load: K (swizzled) + V^T (padded), tf32 RN rounded
        #pragma unroll
        for (int it = 0; it < 4; it++) {
            int f = tid + it * 128;          // 0..511
            int j = f >> 3;                  // key
            int d4 = f & 7;                  // 16B chunk
            const float* src = qkv + kv_base0 + (size_t)(kt * 64 + j) * kv_stride + 32 + d4 * 4;
            float4 kvv = *(const float4*)src;
            float4 rr;
            rr.x = tf32_rn(kvv.x); rr.y = tf32_rn(kvv.y);
            rr.z = tf32_rn(kvv.z); rr.w = tf32_rn(kvv.w);
            uint32_t off = (uint32_t)(j * 128 + d4 * 16);
            *(float4*)((char*)Ks + (off ^ ((off >> 3) & 0x70))) = rr;

            float4 vv = *(const float4*)(src + 32);
            Vt[d4 * 4 + 0][j] = tf32_rn(vv.x);
            Vt[d4 * 4 + 1][j] = tf32_rn(vv.y);
            Vt[d4 * 4 + 2][j] = tf32_rn(vv.z);
            Vt[d4 * 4 + 3][j] = tf32_rn(vv.w);
        }
        __syncthreads();

        // --- S = Q K^T  (8 ntiles of 8 keys) ---
        float sfr[8][4];
        #pragma unroll
        for (int nt = 0; nt < 8; nt++)
            #pragma unroll
            for (int r = 0; r < 4; r++) sfr[nt][r] = 0.0f;

        #pragma unroll
        for (int ks = 0; ks < 4; ks++) {
            const uint32_t co = ((uint32_t)(ks * 32) + kchunk) ^ mask;
            uint32_t kfr[4][4];
            #pragma unroll
            for (int g = 0; g < 4; g++)
                LDSM_X4(kfr[g], kbase + (uint32_t)(g * 16 * 128) + krow + co);
            #pragma unroll
            for (int nt = 0; nt < 8; nt++)
                mma_tf32(sfr[nt], qfr[ks], &kfr[nt >> 1][(nt & 1) * 2]);
        }

        // --- online softmax on C fragments ---
        float mx_lo = sfr[0][0], mx_hi = sfr[0][2];
        #pragma unroll
        for (int nt = 0; nt < 8; nt++) {
            mx_lo = fmaxf(mx_lo, fmaxf(sfr[nt][0], sfr[nt][1]));
            mx_hi = fmaxf(mx_hi, fmaxf(sfr[nt][2], sfr[nt][3]));
        }
        mx_lo = fmaxf(mx_lo, __shfl_xor_sync(0xffffffffu, mx_lo, 1));
        mx_lo = fmaxf(mx_lo, __shfl_xor_sync(0xffffffffu, mx_lo, 2));
        mx_hi = fmaxf(mx_hi, __shfl_xor_sync(0xffffffffu, mx_hi, 1));
        mx_hi = fmaxf(mx_hi, __shfl_xor_sync(0xffffffffu, mx_hi, 2));

        const float nm_lo = fmaxf(m_lo, mx_lo);
        const float nm_hi = fmaxf(m_hi, mx_hi);
        const float corr_lo = __expf(m_lo - nm_lo);   // exp(-inf)=0 first tile
        const float corr_hi = __expf(m_hi - nm_hi);
        m_lo = nm_lo; m_hi = nm_hi;

        float ps_lo = 0.0f, ps_hi = 0.0f;
        {
            const int rl = (lane >> 2);
            const int cb = 2 * (lane & 3);
            float* prow_lo = Pw + rl * VPAD + cb;
            float* prow_hi = Pw + (rl + 8) * VPAD + cb;
            #pragma unroll
            for (int nt = 0; nt < 8; nt++) {
                float p0 = __expf(sfr[nt][0] - m_lo);
                float p1 = __expf(sfr[nt][1] - m_lo);
                float p2 = __expf(sfr[nt][2] - m_hi);
                float p3 = __expf(sfr[nt][3] - m_hi);
                ps_lo += p0 + p1;
                ps_hi += p2 + p3;
                float2 w0; w0.x = tf32_rn(p0); w0.y = tf32_rn(p1);
                float2 w1; w1.x = tf32_rn(p2); w1.y = tf32_rn(p3);
                *(float2*)(prow_lo + nt * 8) = w0;
                *(float2*)(prow_hi + nt * 8) = w1;
            }
        }
        l_lo = l_lo * corr_lo + ps_lo;
        l_hi = l_hi * corr_hi + ps_hi;
        #pragma unroll
        for (int nd = 0; nd < 4; nd++) {
            ofr[nd][0] *= corr_lo; ofr[nd][1] *= corr_lo;
            ofr[nd][2] *= corr_hi; ofr[nd][3] *= corr_hi;
        }
        __syncwarp();

        // --- O += P V  (ksteps over 64 keys, ntiles over HD=32) ---
        {
            const int rl = (lane >> 2);
            const int cl = (lane & 3);
            #pragma unroll
            for (int kk = 0; kk < 8; kk++) {
                uint32_t afr[4];
                afr[0] = Pwu[rl * VPAD + kk * 8 + cl];
                afr[1] = Pwu[(rl + 8) * VPAD + kk * 8 + cl];
                afr[2] = Pwu[rl * VPAD + kk * 8 + cl + 4];
                afr[3] = Pwu[(rl + 8) * VPAD + kk * 8 + cl + 4];
                #pragma unroll
                for (int nd = 0; nd < 4; nd++) {
                    uint32_t bfr[2];
                    bfr[0] = Vtu[(nd * 8 + rl) * VPAD + kk * 8 + cl];
                    bfr[1] = Vtu[(nd * 8 + rl) * VPAD + kk * 8 + cl + 4];
                    mma_tf32(ofr[nd], afr, bfr);
                }
            }
        }
    }

    // final l reduction across quad + store
    l_lo += __shfl_xor_sync(0xffffffffu, l_lo, 1);
    l_lo += __shfl_xor_sync(0xffffffffu, l_lo, 2);
    l_hi += __shfl_xor_sync(0xffffffffu, l_hi, 1);
    l_hi += __shfl_xor_sync(0xffffffffu, l_hi, 2);
    const float inv_lo = 1.0f / l_lo;
    const float inv_hi = 1.0f / l_hi;

    const int t_lo = qt * 64 + wid * 16 + (lane >> 2);
    const size_t ob_lo = (size_t)(b * TT + t_lo) * EE + h * HD + 2 * (lane & 3);
    const size_t ob_hi = ob_lo + 8 * EE;
    #pragma unroll
    for (int nd = 0; nd < 4; nd++) {
        float2 v0; v0.x = ofr[nd][0] * inv_lo; v0.y = ofr[nd][1] * inv_lo;
        float2 v1; v1.x = ofr[nd][2] * inv_hi; v1.y = ofr[nd][3] * inv_hi;
        *(float2*)&out[ob_lo + nd * 8] = v0;
        *(float2*)&out[ob_hi + nd * 8] = v1;
    }
}

// ---------------------------------------------------------------------------
// Fused residual add + LayerNorm
// ---------------------------------------------------------------------------
__global__ __launch_bounds__(256)
void add_ln_kernel(const float* __restrict__ xin, const float* __restrict__ res,
                   const float* __restrict__ g, const float* __restrict__ beta,
                   float* __restrict__ out) {
    const int row = blockIdx.x;
    const int tid = threadIdx.x;
    const size_t idx = (size_t)row * EE + tid;

    float v = xin[idx] + res[idx];

    __shared__ float red[8];
    float s = v;
    #pragma unroll
    for (int o = 16; o > 0; o >>= 1) s += __shfl_xor_sync(0xffffffffu, s, o);
    if ((tid & 31) == 0) red[tid >> 5] = s;
    __syncthreads();
    float tot = 0.0f;
    #pragma unroll
    for (int i = 0; i < 8; i++) tot += red[i];
    const float mu = tot * (1.0f / (float)EE);
    const float d = v - mu;
    __syncthreads();

    float s2 = d * d;
    #pragma unroll
    for (int o = 16; o > 0; o >>= 1) s2 += __shfl_xor_sync(0xffffffffu, s2, o);
    if ((tid & 31) == 0) red[tid >> 5] = s2;
    __syncthreads();
    float tot2 = 0.0f;
    #pragma unroll
    for (int i = 0; i < 8; i++) tot2 += red[i];
    const float var = tot2 * (1.0f / (float)EE);

    out[idx] = d * rsqrtf(var + EPS) * g[tid] + beta[tid];
}

// ---------------------------------------------------------------------------
// kernel_launch
// ---------------------------------------------------------------------------
extern "C" void kernel_launch(void* const* d_in, const int* in_sizes, int n_in,
                              void* d_out, int out_size) {
    const float* x     = (const float*)d_in[0];
    const float* qkv_w = (const float*)d_in[1];
    const float* qkv_b = (const float*)d_in[2];
    const float* out_w = (const float*)d_in[3];
    const float* out_b = (const float*)d_in[4];
    const float* ff1_w = (const float*)d_in[5];
    const float* ff1_b = (const float*)d_in[6];
    const float* ff2_w = (const float*)d_in[7];
    const float* ff2_b = (const float*)d_in[8];
    const float* ln1_g = (const float*)d_in[9];
    const float* ln1_b = (const float*)d_in[10];
    const float* ln2_g = (const float*)d_in[11];
    const float* ln2_b = (const float*)d_in[12];
    float* outp = (float*)d_out;

    float *gx, *gqkv, *gattn, *gtmp, *gffh, *wq, *wo, *w1, *w2;
    cudaGetSymbolAddress((void**)&gx,   g_x);
    cudaGetSymbolAddress((void**)&gqkv, g_qkv);
    cudaGetSymbolAddress((void**)&gattn,g_attn);
    cudaGetSymbolAddress((void**)&gtmp, g_tmp);
    cudaGetSymbolAddress((void**)&gffh, g_ffh);
    cudaGetSymbolAddress((void**)&wq,   g_qkvw_t);
    cudaGetSymbolAddress((void**)&wo,   g_outw_t);
    cudaGetSymbolAddress((void**)&w1,   g_ff1w_t);
    cudaGetSymbolAddress((void**)&w2,   g_ff2w_t);

    cudaFuncSetAttribute(gemm_tc_kernel, cudaFuncAttributeMaxDynamicSharedMemorySize, GSMEM_TOTAL);

    const dim3 tthr(32, 8);
    transpose_kernel<<<dim3(24, 8, LL), tthr>>>(qkv_w, wq, EE, 3 * EE);
    transpose_kernel<<<dim3(8, 8, LL), tthr>>>(out_w, wo, EE, EE);
    transpose_kernel<<<dim3(32, 8, LL), tthr>>>(ff1_w, w1, EE, FEE * EE);
    transpose_kernel<<<dim3(8, 32, LL), tthr>>>(ff2_w, w2, FEE * EE, EE);

    pe_kernel<<<(MROWS * EE + 255) / 256, 256>>>(x, gx);

    for (int i = 0; i < LL; i++) {
        // qkv = x @ qkv_w + b    (8192 x 768, K=256)
        gemm_tc_kernel<<<dim3(6, 64), 256, GSMEM_TOTAL>>>(
            gx, wq + (size_t)i * 3 * EE * EE, qkv_b + (size_t)i * 3 * EE,
            gqkv, 3 * EE, EE, 0);

        // tensor-core flash attention
        attn_tc_kernel<<<dim3(TT / 64, BB * HH), 128>>>(gqkv, gattn);

        // proj = attn @ out_w + b  (8192 x 256, K=256)
        gemm_tc_kernel<<<dim3(2, 64), 256, GSMEM_TOTAL>>>(
            gattn, wo + (size_t)i * EE * EE, out_b + (size_t)i * EE,
            gtmp, EE, EE, 0);

        add_ln_kernel<<<MROWS, 256>>>(gx, gtmp,
            ln1_g + (size_t)i * EE, ln1_b + (size_t)i * EE, gx);

        // h = relu(x @ ff1_w + b)  (8192 x 1024, K=256)
        gemm_tc_kernel<<<dim3(8, 64), 256, GSMEM_TOTAL>>>(
            gx, w1 + (size_t)i * FEE * EE * EE, ff1_b + (size_t)i * FEE * EE,
            gffh, FEE * EE, EE, 1);

        // ff = h @ ff2_w + b       (8192 x 256, K=1024)
        gemm_tc_kernel<<<dim3(2, 64), 256, GSMEM_TOTAL>>>(
            gffh, w2 + (size_t)i * FEE * EE * EE, ff2_b + (size_t)i * EE,
            gtmp, EE, FEE * EE, 0);

        float* dst = (i == LL - 1) ? outp : gx;
        add_ln_kernel<<<MROWS, 256>>>(gx, gtmp,
            ln2_g + (size_t)i * EE, ln2_b + (size_t)i * EE, dst);
    }
}

// round 6
// speedup vs baseline: 5.4003x; 1.0336x over previous
#include <cuda_runtime.h>
#include <cuda_bf16.h>
#include <math.h>
#include <cstdint>

// Problem constants
#define BB 4
#define TT 2048
#define EE 256
#define HH 8
#define HD 32
#define FEE 4
#define LL 4
#define MROWS (BB*TT)          // 8192
#define EPS 1e-5f

// ---------------------------------------------------------------------------
// Scratch (device globals; no runtime allocation allowed)
// ---------------------------------------------------------------------------
__device__ float g_x   [MROWS * EE];
__device__ float g_qkv [MROWS * 3 * EE];
__device__ float g_attn[MROWS * EE];
__device__ float g_ffh [MROWS * FEE * EE];
// transposed weights [N, K] row-major, per layer (tf32-rounded)
__device__ float g_qkvw_t[LL * 3 * EE * EE];
__device__ float g_outw_t[LL * EE * EE];
__device__ float g_ff1w_t[LL * FEE * EE * EE];
__device__ float g_ff2w_t[LL * FEE * EE * EE];

// ---------------------------------------------------------------------------
// PTX helpers (sm_80-era only; target is plain sm_103 — no tcgen05!)
// ---------------------------------------------------------------------------
__device__ __forceinline__ uint32_t smem_u32(const void* p) {
    uint32_t a;
    asm("{ .reg .u64 t; cvta.to.shared.u64 t, %1; cvt.u32.u64 %0, t; }" : "=r"(a) : "l"(p));
    return a;
}

__device__ __forceinline__ float tf32_rn(float x) {
    uint32_t u;
    asm("cvt.rna.tf32.f32 %0, %1;" : "=r"(u) : "f"(x));
    return __uint_as_float(u);
}

#define CP_ASYNC16(dst, src) \
    asm volatile("cp.async.cg.shared.global [%0], [%1], 16;\n" :: "r"(dst), "l"(src))
#define CP_COMMIT() asm volatile("cp.async.commit_group;\n" ::)
#define CP_WAIT1() asm volatile("cp.async.wait_group 1;\n" ::)
#define CP_WAIT0() asm volatile("cp.async.wait_group 0;\n" ::)

#define LDSM_X4(r, addr) \
    asm volatile("ldmatrix.sync.aligned.m8n8.x4.shared.b16 {%0,%1,%2,%3}, [%4];" \
        : "=r"((r)[0]), "=r"((r)[1]), "=r"((r)[2]), "=r"((r)[3]) : "r"(addr))

__device__ __forceinline__ void mma_tf32(float c[4], const uint32_t a[4], const uint32_t b[2]) {
    asm volatile("mma.sync.aligned.m16n8k8.row.col.f32.tf32.tf32.f32 "
        "{%0,%1,%2,%3}, {%4,%5,%6,%7}, {%8,%9}, {%0,%1,%2,%3};"
        : "+f"(c[0]), "+f"(c[1]), "+f"(c[2]), "+f"(c[3])
        : "r"(a[0]), "r"(a[1]), "r"(a[2]), "r"(a[3]), "r"(b[0]), "r"(b[1]));
}

// ---------------------------------------------------------------------------
// Positional encoding
// ---------------------------------------------------------------------------
__global__ void pe_kernel(const float* __restrict__ x, float* __restrict__ out) {
    int idx = blockIdx.x * blockDim.x + threadIdx.x;
    if (idx >= MROWS * EE) return;
    int e = idx & (EE - 1);
    int t = (idx / EE) & (TT - 1);
    int i = (e < 128) ? e : e - 128;
    float f = __expf(-((2.0f * (float)i) * (1.0f / (float)EE)) * 9.210340371976184f);
    float ang = (float)t * f;
    float pe = (e < 128) ? sinf(ang) : cosf(ang);
    out[idx] = x[idx] + pe;
}

// ---------------------------------------------------------------------------
// Weight transpose + tf32 round-to-nearest: in [l][K][N] -> out [l][N][K]
// ---------------------------------------------------------------------------
__global__ void transpose_kernel(const float* __restrict__ in, float* __restrict__ out,
                                 int K, int N) {
    __shared__ float tile[32][33];
    const size_t plane = (size_t)K * N;
    const float* ip = in + blockIdx.z * plane;
    float* op = out + blockIdx.z * plane;
    int n0 = blockIdx.x * 32, k0 = blockIdx.y * 32;
    int tx = threadIdx.x, ty = threadIdx.y;
    #pragma unroll
    for (int i = 0; i < 32; i += 8)
        tile[ty + i][tx] = ip[(size_t)(k0 + ty + i) * N + n0 + tx];
    __syncthreads();
    #pragma unroll
    for (int i = 0; i < 32; i += 8)
        op[(size_t)(n0 + ty + i) * K + k0 + tx] = tf32_rn(tile[tx][ty + i]);
}

// ---------------------------------------------------------------------------
// tf32 mma.sync GEMM: C[M,N] = A[M,K] @ Bt[N,K]^T + bias  (optional ReLU)
// Block tile 128x128, BK=32, 8 warps (2m x 4n), 3-stage cp.async pipeline.
// ---------------------------------------------------------------------------
#define GSTAGE 32768           // A (16KB) + B (16KB) per stage
#define GSMEM_TOTAL (3 * GSTAGE)

__device__ __forceinline__ void gemm_load_stage(uint32_t sbase, const float* A, const float* Bt,
                                                int K, int bm, int bn, int kt, int tid) {
    uint32_t abuf = sbase + (uint32_t)(kt % 3) * GSTAGE;
    uint32_t bbuf = abuf + 16384;
    const float* ap = A + (size_t)bm * K + kt * 32;
    const float* bp = Bt + (size_t)bn * K + kt * 32;
    #pragma unroll
    for (int i = 0; i < 4; i++) {
        int f = tid + i * 256;
        int r = f >> 3;
        int cB = (f & 7) * 16;
        uint32_t off = (uint32_t)(r * 128 + cB);
        uint32_t sw = off ^ ((off >> 3) & 0x70);
        CP_ASYNC16(abuf + sw, ap + (size_t)r * K + (cB >> 2));
        CP_ASYNC16(bbuf + sw, bp + (size_t)r * K + (cB >> 2));
    }
    CP_COMMIT();
}

__global__ __launch_bounds__(256)
void gemm_tc_kernel(const float* __restrict__ A, const float* __restrict__ Bt,
                    const float* __restrict__ bias, float* __restrict__ C,
                    int N, int K, int relu) {
    extern __shared__ char smem[];
    uint32_t sbase = smem_u32(smem);
    const int tid = threadIdx.x;
    const int wid = tid >> 5;
    const int lane = tid & 31;
    const int warpM = wid & 1;
    const int warpN = wid >> 1;
    const int bn = blockIdx.x * 128;
    const int bm = blockIdx.y * 128;

    float acc[4][4][4];
    #pragma unroll
    for (int mt = 0; mt < 4; mt++)
        #pragma unroll
        for (int nt = 0; nt < 4; nt++)
            #pragma unroll
            for (int r = 0; r < 4; r++) acc[mt][nt][r] = 0.0f;

    const uint32_t mask = (uint32_t)(lane & 7) << 4;
    uint32_t arowb[4];
    #pragma unroll
    for (int mt = 0; mt < 4; mt++)
        arowb[mt] = (uint32_t)(warpM * 64 + (lane & 15) + mt * 16) * 128;
    const uint32_t achunk = (uint32_t)(lane >> 4) * 16;
    uint32_t browb[2];
    #pragma unroll
    for (int nh = 0; nh < 2; nh++)
        browb[nh] = (uint32_t)(warpN * 32 + nh * 16 + (lane & 7) + ((lane >> 4) << 3)) * 128;
    const uint32_t bchunk = (uint32_t)((lane >> 3) & 1) * 16;

    const int nk = K / 32;
    gemm_load_stage(sbase, A, Bt, K, bm, bn, 0, tid);
    gemm_load_stage(sbase, A, Bt, K, bm, bn, 1, tid);

    for (int kt = 0; kt < nk; kt++) {
        if (kt + 1 < nk) { CP_WAIT1(); } else { CP_WAIT0(); }
        __syncthreads();
        if (kt + 2 < nk) gemm_load_stage(sbase, A, Bt, K, bm, bn, kt + 2, tid);

        const uint32_t ab = sbase + (uint32_t)(kt % 3) * GSTAGE;
        const uint32_t bb = ab + 16384;

        #pragma unroll
        for (int ks = 0; ks < 4; ks++) {
            const uint32_t aco = ((uint32_t)(ks * 32) + achunk) ^ mask;
            const uint32_t bco = ((uint32_t)(ks * 32) + bchunk) ^ mask;

            uint32_t afr[4][4], bfr[2][4];
            #pragma unroll
            for (int mt = 0; mt < 4; mt++) LDSM_X4(afr[mt], ab + arowb[mt] + aco);
            #pragma unroll
            for (int nh = 0; nh < 2; nh++) LDSM_X4(bfr[nh], bb + browb[nh] + bco);

            #pragma unroll
            for (int mt = 0; mt < 4; mt++)
                #pragma unroll
                for (int r = 0; r < 4; r++)
                    afr[mt][r] = __float_as_uint(tf32_rn(__uint_as_float(afr[mt][r])));

            #pragma unroll
            for (int mt = 0; mt < 4; mt++)
                #pragma unroll
                for (int nt = 0; nt < 4; nt++)
                    mma_tf32(acc[mt][nt], afr[mt], &bfr[nt >> 1][(nt & 1) * 2]);
        }
    }

    #pragma unroll
    for (int mt = 0; mt < 4; mt++) {
        const int row0 = bm + warpM * 64 + mt * 16 + (lane >> 2);
        #pragma unroll
        for (int nt = 0; nt < 4; nt++) {
            const int col = bn + warpN * 32 + nt * 8 + (lane & 3) * 2;
            const float2 bi = *(const float2*)&bias[col];
            float v0 = acc[mt][nt][0] + bi.x;
            float v1 = acc[mt][nt][1] + bi.y;
            float v2 = acc[mt][nt][2] + bi.x;
            float v3 = acc[mt][nt][3] + bi.y;
            if (relu) {
                v0 = fmaxf(v0, 0.0f); v1 = fmaxf(v1, 0.0f);
                v2 = fmaxf(v2, 0.0f); v3 = fmaxf(v3, 0.0f);
            }
            float2 p0; p0.x = v0; p0.y = v1;
            float2 p1; p1.x = v2; p1.y = v3;
            *(float2*)&C[(size_t)row0 * N + col] = p0;
            *(float2*)&C[(size_t)(row0 + 8) * N + col] = p1;
        }
    }
}

// ---------------------------------------------------------------------------
// Fused GEMM (N=256) + bias + residual + LayerNorm:
//   out = LN(res + A @ Bt^T + bias) * g + beta
// BM=64, BN=256 (full row per CTA), 8 warps (2m x 4n), warp tile m32 n64.
// 3-stage cp.async pipeline. Row stats via quad-shfl + smem cross-warp.
// ---------------------------------------------------------------------------
#define LSTAGE 40960           // A (8KB) + B (32KB)
#define LSMEM_TOTAL (3 * LSTAGE)

__device__ __forceinline__ void gemmln_load_stage(uint32_t sbase, const float* A, const float* Bt,
                                                  int K, int bm, int kt, int tid) {
    uint32_t abuf = sbase + (uint32_t)(kt % 3) * LSTAGE;
    uint32_t bbuf = abuf + 8192;
    const float* ap = A + (size_t)bm * K + kt * 32;
    const float* bp = Bt + kt * 32;
    #pragma unroll
    for (int i = 0; i < 2; i++) {
        int f = tid + i * 256;           // 0..511 -> A 64 rows x 8 chunks
        int r = f >> 3;
        int cB = (f & 7) * 16;
        uint32_t off = (uint32_t)(r * 128 + cB);
        uint32_t sw = off ^ ((off >> 3) & 0x70);
        CP_ASYNC16(abuf + sw, ap + (size_t)r * K + (cB >> 2));
    }
    #pragma unroll
    for (int i = 0; i < 8; i++) {
        int f = tid + i * 256;           // 0..2047 -> B 256 rows x 8 chunks
        int r = f >> 3;
        int cB = (f & 7) * 16;
        uint32_t off = (uint32_t)(r * 128 + cB);
        uint32_t sw = off ^ ((off >> 3) & 0x70);
        CP_ASYNC16(bbuf + sw, bp + (size_t)r * K + (cB >> 2));
    }
    CP_COMMIT();
}

__global__ __launch_bounds__(256)
void gemm_ln_kernel(const float* __restrict__ A, const float* __restrict__ Bt,
                    const float* __restrict__ bias, const float* __restrict__ res,
                    const float* __restrict__ g, const float* __restrict__ beta,
                    float* __restrict__ out, int K) {
    extern __shared__ char smem[];
    uint32_t sbase = smem_u32(smem);
    const int tid = threadIdx.x;
    const int wid = tid >> 5;
    const int lane = tid & 31;
    const int warpM = wid & 1;          // 2 warps over M (32 rows each)
    const int warpN = wid >> 1;         // 4 warps over N (64 cols each)
    const int bm = blockIdx.x * 64;

    float acc[2][8][4];
    #pragma unroll
    for (int mt = 0; mt < 2; mt++)
        #pragma unroll
        for (int nt = 0; nt < 8; nt++)
            #pragma unroll
            for (int r = 0; r < 4; r++) acc[mt][nt][r] = 0.0f;

    const uint32_t mask = (uint32_t)(lane & 7) << 4;
    uint32_t arowb[2];
    #pragma unroll
    for (int mt = 0; mt < 2; mt++)
        arowb[mt] = (uint32_t)(warpM * 32 + mt * 16 + (lane & 15)) * 128;
    const uint32_t achunk = (uint32_t)(lane >> 4) * 16;
    uint32_t browb[4];
    #pragma unroll
    for (int nh = 0; nh < 4; nh++)
        browb[nh] = (uint32_t)(warpN * 64 + nh * 16 + (lane & 7) + ((lane >> 4) << 3)) * 128;
    const uint32_t bchunk = (uint32_t)((lane >> 3) & 1) * 16;

    const int nk = K / 32;
    gemmln_load_stage(sbase, A, Bt, K, bm, 0, tid);
    gemmln_load_stage(sbase, A, Bt, K, bm, 1, tid);

    for (int kt = 0; kt < nk; kt++) {
        if (kt + 1 < nk) { CP_WAIT1(); } else { CP_WAIT0(); }
        __syncthreads();
        if (kt + 2 < nk) gemmln_load_stage(sbase, A, Bt, K, bm, kt + 2, tid);

        const uint32_t ab = sbase + (uint32_t)(kt % 3) * LSTAGE;
        const uint32_t bb = ab + 8192;

        #pragma unroll
        for (int ks = 0; ks < 4; ks++) {
            const uint32_t aco = ((uint32_t)(ks * 32) + achunk) ^ mask;
            const uint32_t bco = ((uint32_t)(ks * 32) + bchunk) ^ mask;

            uint32_t afr[2][4], bfr[4][4];
            #pragma unroll
            for (int mt = 0; mt < 2; mt++) LDSM_X4(afr[mt], ab + arowb[mt] + aco);
            #pragma unroll
            for (int nh = 0; nh < 4; nh++) LDSM_X4(bfr[nh], bb + browb[nh] + bco);

            #pragma unroll
            for (int mt = 0; mt < 2; mt++)
                #pragma unroll
                for (int r = 0; r < 4; r++)
                    afr[mt][r] = __float_as_uint(tf32_rn(__uint_as_float(afr[mt][r])));

            #pragma unroll
            for (int mt = 0; mt < 2; mt++)
                #pragma unroll
                for (int nt = 0; nt < 8; nt++)
                    mma_tf32(acc[mt][nt], afr[mt], &bfr[nt >> 1][(nt & 1) * 2]);
        }
    }
    __syncthreads();   // smem free for reductions now

    // --- epilogue: v = acc + bias + res; row stats; LN; store ---
    float* redS = (float*)smem;           // [64][4]
    float* redQ = (float*)smem + 256;     // [64][4]

    const int rl = lane >> 2;
    const int cl = (lane & 3) * 2;
    float sum[2][2] = {{0,0},{0,0}}, sq[2][2] = {{0,0},{0,0}};

    #pragma unroll
    for (int mt = 0; mt < 2; mt++) {
        const int rlo = bm + warpM * 32 + mt * 16 + rl;
        #pragma unroll
        for (int nt = 0; nt < 8; nt++) {
            const int col = warpN * 64 + nt * 8 + cl;
            const float2 bi = *(const float2*)&bias[col];
            const float2 r0 = *(const float2*)&res[(size_t)rlo * EE + col];
            const float2 r1 = *(const float2*)&res[(size_t)(rlo + 8) * EE + col];
            float v0 = acc[mt][nt][0] + bi.x + r0.x;
            float v1 = acc[mt][nt][1] + bi.y + r0.y;
            float v2 = acc[mt][nt][2] + bi.x + r1.x;
            float v3 = acc[mt][nt][3] + bi.y + r1.y;
            acc[mt][nt][0] = v0; acc[mt][nt][1] = v1;
            acc[mt][nt][2] = v2; acc[mt][nt][3] = v3;
            sum[mt][0] += v0 + v1;     sum[mt][1] += v2 + v3;
            sq[mt][0]  += v0*v0 + v1*v1; sq[mt][1] += v2*v2 + v3*v3;
        }
    }
    // quad reduce (over lane&3)
    #pragma unroll
    for (int mt = 0; mt < 2; mt++)
        #pragma unroll
        for (int hh = 0; hh < 2; hh++) {
            sum[mt][hh] += __shfl_xor_sync(0xffffffffu, sum[mt][hh], 1);
            sum[mt][hh] += __shfl_xor_sync(0xffffffffu, sum[mt][hh], 2);
            sq[mt][hh]  += __shfl_xor_sync(0xffffffffu, sq[mt][hh], 1);
            sq[mt][hh]  += __shfl_xor_sync(0xffffffffu, sq[mt][hh], 2);
        }
    if ((lane & 3) == 0) {
        #pragma unroll
        for (int mt = 0; mt < 2; mt++) {
            int rloc = warpM * 32 + mt * 16 + rl;
            redS[rloc * 4 + warpN] = sum[mt][0];
            redQ[rloc * 4 + warpN] = sq[mt][0];
            redS[(rloc + 8) * 4 + warpN] = sum[mt][1];
            redQ[(rloc + 8) * 4 + warpN] = sq[mt][1];
        }
    }
    __syncthreads();

    #pragma unroll
    for (int mt = 0; mt < 2; mt++) {
        #pragma unroll
        for (int hh = 0; hh < 2; hh++) {
            const int rloc = warpM * 32 + mt * 16 + rl + hh * 8;
            float ts = redS[rloc * 4 + 0] + redS[rloc * 4 + 1]
                     + redS[rloc * 4 + 2] + redS[rloc * 4 + 3];
            float tq = redQ[rloc * 4 + 0] + redQ[rloc * 4 + 1]
                     + redQ[rloc * 4 + 2] + redQ[rloc * 4 + 3];
            const float mu = ts * (1.0f / (float)EE);
            const float var = tq * (1.0f / (float)EE) - mu * mu;
            const float inv = rsqrtf(var + EPS);
            const int row = bm + rloc;
            #pragma unroll
            for (int nt = 0; nt < 8; nt++) {
                const int col = warpN * 64 + nt * 8 + cl;
                const float2 gg = *(const float2*)&g[col];
                const float2 bb = *(const float2*)&beta[col];
                float v0 = acc[mt][nt][2 * hh + 0];
                float v1 = acc[mt][nt][2 * hh + 1];
                float2 o;
                o.x = (v0 - mu) * inv * gg.x + bb.x;
                o.y = (v1 - mu) * inv * gg.y + bb.y;
                *(float2*)&out[(size_t)row * EE + col] = o;
            }
        }
    }
}

// ---------------------------------------------------------------------------
// Tensor-core flash attention (tf32 mma.sync).
// Block = (b,h) x 64-query tile; 4 warps x 16 rows. KV tiles of 64 keys.
// qkv layout: [B,T,H,3,HD] -> (b*T+t)*768 + h*96 + s*32 + d
// ---------------------------------------------------------------------------
#define VPAD 68

__global__ __launch_bounds__(128)
void attn_tc_kernel(const float* __restrict__ qkv, float* __restrict__ out) {
    __shared__ float Ks[64 * 32];            // SW128-swizzled, 128B rows
    __shared__ float Vt[32][VPAD];           // V^T [d][key], padded
    __shared__ float Pb[4][16 * VPAD];       // per-warp P [16][VPAD]

    const int tid = threadIdx.x;
    const int wid = tid >> 5;
    const int lane = tid & 31;
    const int qt = blockIdx.x;
    const int bh = blockIdx.y;
    const int h = bh & (HH - 1);
    const int b = bh >> 3;

    const uint32_t kbase = smem_u32(Ks);
    const float scale = 0.17677669529663687f;   // 1/sqrt(32)

    uint32_t qfr[4][4];
    {
        const int r_lo = qt * 64 + wid * 16 + (lane >> 2);
        const size_t base_lo = (size_t)(b * TT + r_lo) * 768 + h * 96;
        const size_t base_hi = base_lo + 8 * 768;
        #pragma unroll
        for (int ks = 0; ks < 4; ks++) {
            int c0 = ks * 8 + (lane & 3);
            qfr[ks][0] = __float_as_uint(tf32_rn(qkv[base_lo + c0] * scale));
            qfr[ks][1] = __float_as_uint(tf32_rn(qkv[base_hi + c0] * scale));
            qfr[ks][2] = __float_as_uint(tf32_rn(qkv[base_lo + c0 + 4] * scale));
            qfr[ks][3] = __float_as_uint(tf32_rn(qkv[base_hi + c0 + 4] * scale));
        }
    }

    float ofr[4][4];
    #pragma unroll
    for (int nd = 0; nd < 4; nd++)
        #pragma unroll
        for (int r = 0; r < 4; r++) ofr[nd][r] = 0.0f;
    float m_lo = -INFINITY, m_hi = -INFINITY, l_lo = 0.0f, l_hi = 0.0f;

    const uint32_t mask = (uint32_t)(lane & 7) << 4;
    const uint32_t krow = (uint32_t)((lane & 7) + ((lane >> 4) << 3)) * 128;
    const uint32_t kchunk = (uint32_t)((lane >> 3) & 1) * 16;

    float* Pw = &Pb[wid][0];
    const uint32_t* Pwu = (const uint32_t*)Pw;
    const uint32_t* Vtu = (const uint32_t*)&Vt[0][0];

    const size_t kv_stride = 768;
    const size_t kv_base0 = (size_t)(b * TT) * 768 + h * 96;

    for (int kt = 0; kt < TT / 64; kt++) {
        __syncthreads();
        #pragma unroll
        for (int it = 0; it < 4; it++) {
            int f = tid + it * 128;
            int j = f >> 3;
            int d4 = f & 7;
            const float* src = qkv + kv_base0 + (size_t)(kt * 64 + j) * kv_stride + 32 + d4 * 4;
            float4 kvv = *(const float4*)src;
            float4 rr;
            rr.x = tf32_rn(kvv.x); rr.y = tf32_rn(kvv.y);
            rr.z = tf32_rn(kvv.z); rr.w = tf32_rn(kvv.w);
            uint32_t off = (uint32_t)(j * 128 + d4 * 16);
            *(float4*)((char*)Ks + (off ^ ((off >> 3) & 0x70))) = rr;

            float4 vv = *(const float4*)(src + 32);
            Vt[d4 * 4 + 0][j] = tf32_rn(vv.x);
            Vt[d4 * 4 + 1][j] = tf32_rn(vv.y);
            Vt[d4 * 4 + 2][j] = tf32_rn(vv.z);
            Vt[d4 * 4 + 3][j] = tf32_rn(vv.w);
        }
        __syncthreads();

        float sfr[8][4];
        #pragma unroll
        for (int nt = 0; nt < 8; nt++)
            #pragma unroll
            for (int r = 0; r < 4; r++) sfr[nt][r] = 0.0f;

        #pragma unroll
        for (int ks = 0; ks < 4; ks++) {
            const uint32_t co = ((uint32_t)(ks * 32) + kchunk) ^ mask;
            uint32_t kfr[4][4];
            #pragma unroll
            for (int gI = 0; gI < 4; gI++)
                LDSM_X4(kfr[gI], kbase + (uint32_t)(gI * 16 * 128) + krow + co);
            #pragma unroll
            for (int nt = 0; nt < 8; nt++)
                mma_tf32(sfr[nt], qfr[ks], &kfr[nt >> 1][(nt & 1) * 2]);
        }

        float mx_lo = sfr[0][0], mx_hi = sfr[0][2];
        #pragma unroll
        for (int nt = 0; nt < 8; nt++) {
            mx_lo = fmaxf(mx_lo, fmaxf(sfr[nt][0], sfr[nt][1]));
            mx_hi = fmaxf(mx_hi, fmaxf(sfr[nt][2], sfr[nt][3]));
        }
        mx_lo = fmaxf(mx_lo, __shfl_xor_sync(0xffffffffu, mx_lo, 1));
        mx_lo = fmaxf(mx_lo, __shfl_xor_sync(0xffffffffu, mx_lo, 2));
        mx_hi = fmaxf(mx_hi, __shfl_xor_sync(0xffffffffu, mx_hi, 1));
        mx_hi = fmaxf(mx_hi, __shfl_xor_sync(0xffffffffu, mx_hi, 2));

        const float nm_lo = fmaxf(m_lo, mx_lo);
        const float nm_hi = fmaxf(m_hi, mx_hi);
        const float corr_lo = __expf(m_lo - nm_lo);
        const float corr_hi = __expf(m_hi - nm_hi);
        m_lo = nm_lo; m_hi = nm_hi;

        float ps_lo = 0.0f, ps_hi = 0.0f;
        {
            const int rl = (lane >> 2);
            const int cb = 2 * (lane & 3);
            float* prow_lo = Pw + rl * VPAD + cb;
            float* prow_hi = Pw + (rl + 8) * VPAD + cb;
            #pragma unroll
            for (int nt = 0; nt < 8; nt++) {
                float p0 = __expf(sfr[nt][0] - m_lo);
                float p1 = __expf(sfr[nt][1] - m_lo);
                float p2 = __expf(sfr[nt][2] - m_hi);
                float p3 = __expf(sfr[nt][3] - m_hi);
                ps_lo += p0 + p1;
                ps_hi += p2 + p3;
                float2 w0; w0.x = tf32_rn(p0); w0.y = tf32_rn(p1);
                float2 w1; w1.x = tf32_rn(p2); w1.y = tf32_rn(p3);
                *(float2*)(prow_lo + nt * 8) = w0;
                *(float2*)(prow_hi + nt * 8) = w1;
            }
        }
        l_lo = l_lo * corr_lo + ps_lo;
        l_hi = l_hi * corr_hi + ps_hi;
        #pragma unroll
        for (int nd = 0; nd < 4; nd++) {
            ofr[nd][0] *= corr_lo; ofr[nd][1] *= corr_lo;
            ofr[nd][2] *= corr_hi; ofr[nd][3] *= corr_hi;
        }
        __syncwarp();

        {
            const int rl = (lane >> 2);
            const int cl = (lane & 3);
            #pragma unroll
            for (int kk = 0; kk < 8; kk++) {
                uint32_t afr[4];
                afr[0] = Pwu[rl * VPAD + kk * 8 + cl];
                afr[1] = Pwu[(rl + 8) * VPAD + kk * 8 + cl];
                afr[2] = Pwu[rl * VPAD + kk * 8 + cl + 4];
                afr[3] = Pwu[(rl + 8) * VPAD + kk * 8 + cl + 4];
                #pragma unroll
                for (int nd = 0; nd < 4; nd++) {
                    uint32_t bfr[2];
                    bfr[0] = Vtu[(nd * 8 + rl) * VPAD + kk * 8 + cl];
                    bfr[1] = Vtu[(nd * 8 + rl) * VPAD + kk * 8 + cl + 4];
                    mma_tf32(ofr[nd], afr, bfr);
                }
            }
        }
    }

    l_lo += __shfl_xor_sync(0xffffffffu, l_lo, 1);
    l_lo += __shfl_xor_sync(0xffffffffu, l_lo, 2);
    l_hi += __shfl_xor_sync(0xffffffffu, l_hi, 1);
    l_hi += __shfl_xor_sync(0xffffffffu, l_hi, 2);
    const float inv_lo = 1.0f / l_lo;
    const float inv_hi = 1.0f / l_hi;

    const int t_lo = qt * 64 + wid * 16 + (lane >> 2);
    const size_t ob_lo = (size_t)(b * TT + t_lo) * EE + h * HD + 2 * (lane & 3);
    const size_t ob_hi = ob_lo + 8 * EE;
    #pragma unroll
    for (int nd = 0; nd < 4; nd++) {
        float2 v0; v0.x = ofr[nd][0] * inv_lo; v0.y = ofr[nd][1] * inv_lo;
        float2 v1; v1.x = ofr[nd][2] * inv_hi; v1.y = ofr[nd][3] * inv_hi;
        *(float2*)&out[ob_lo + nd * 8] = v0;
        *(float2*)&out[ob_hi + nd * 8] = v1;
    }
}

// ---------------------------------------------------------------------------
// kernel_launch
// ---------------------------------------------------------------------------
extern "C" void kernel_launch(void* const* d_in, const int* in_sizes, int n_in,
                              void* d_out, int out_size) {
    const float* x     = (const float*)d_in[0];
    const float* qkv_w = (const float*)d_in[1];
    const float* qkv_b = (const float*)d_in[2];
    const float* out_w = (const float*)d_in[3];
    const float* out_b = (const float*)d_in[4];
    const float* ff1_w = (const float*)d_in[5];
    const float* ff1_b = (const float*)d_in[6];
    const float* ff2_w = (const float*)d_in[7];
    const float* ff2_b = (const float*)d_in[8];
    const float* ln1_g = (const float*)d_in[9];
    const float* ln1_b = (const float*)d_in[10];
    const float* ln2_g = (const float*)d_in[11];
    const float* ln2_b = (const float*)d_in[12];
    float* outp = (float*)d_out;

    float *gx, *gqkv, *gattn, *gffh, *wq, *wo, *w1, *w2;
    cudaGetSymbolAddress((void**)&gx,   g_x);
    cudaGetSymbolAddress((void**)&gqkv, g_qkv);
    cudaGetSymbolAddress((void**)&gattn,g_attn);
    cudaGetSymbolAddress((void**)&gffh, g_ffh);
    cudaGetSymbolAddress((void**)&wq,   g_qkvw_t);
    cudaGetSymbolAddress((void**)&wo,   g_outw_t);
    cudaGetSymbolAddress((void**)&w1,   g_ff1w_t);
    cudaGetSymbolAddress((void**)&w2,   g_ff2w_t);

    cudaFuncSetAttribute(gemm_tc_kernel, cudaFuncAttributeMaxDynamicSharedMemorySize, GSMEM_TOTAL);
    cudaFuncSetAttribute(gemm_ln_kernel, cudaFuncAttributeMaxDynamicSharedMemorySize, LSMEM_TOTAL);

    const dim3 tthr(32, 8);
    transpose_kernel<<<dim3(24, 8, LL), tthr>>>(qkv_w, wq, EE, 3 * EE);
    transpose_kernel<<<dim3(8, 8, LL), tthr>>>(out_w, wo, EE, EE);
    transpose_kernel<<<dim3(32, 8, LL), tthr>>>(ff1_w, w1, EE, FEE * EE);
    transpose_kernel<<<dim3(8, 32, LL), tthr>>>(ff2_w, w2, FEE * EE, EE);

    pe_kernel<<<(MROWS * EE + 255) / 256, 256>>>(x, gx);

    for (int i = 0; i < LL; i++) {
        // qkv = x @ qkv_w + b    (8192 x 768, K=256)
        gemm_tc_kernel<<<dim3(6, 64), 256, GSMEM_TOTAL>>>(
            gx, wq + (size_t)i * 3 * EE * EE, qkv_b + (size_t)i * 3 * EE,
            gqkv, 3 * EE, EE, 0);

        // tensor-core flash attention
        attn_tc_kernel<<<dim3(TT / 64, BB * HH), 128>>>(gqkv, gattn);

        // x = LN(x + attn @ out_w + out_b)    (fused)
        gemm_ln_kernel<<<MROWS / 64, 256, LSMEM_TOTAL>>>(
            gattn, wo + (size_t)i * EE * EE, out_b + (size_t)i * EE,
            gx, ln1_g + (size_t)i * EE, ln1_b + (size_t)i * EE, gx, EE);

        // h = relu(x @ ff1_w + b)  (8192 x 1024, K=256)
        gemm_tc_kernel<<<dim3(8, 64), 256, GSMEM_TOTAL>>>(
            gx, w1 + (size_t)i * FEE * EE * EE, ff1_b + (size_t)i * FEE * EE,
            gffh, FEE * EE, EE, 1);

        // x = LN(x + h @ ff2_w + ff2_b)       (fused; K=1024)
        float* dst = (i == LL - 1) ? outp : gx;
        gemm_ln_kernel<<<MROWS / 64, 256, LSMEM_TOTAL>>>(
            gffh, w2 + (size_t)i * FEE * EE * EE, ff2_b + (size_t)i * EE,
            gx, ln2_g + (size_t)i * EE, ln2_b + (size_t)i * EE, dst, FEE * EE);
    }
}

// round 7
// speedup vs baseline: 5.8634x; 1.0858x over previous
#include <cuda_runtime.h>
#include <cuda_bf16.h>
#include <math.h>
#include <cstdint>

// Problem constants
#define BB 4
#define TT 2048
#define EE 256
#define HH 8
#define HD 32
#define FEE 4
#define LL 4
#define MROWS (BB*TT)          // 8192
#define EPS 1e-5f

// ---------------------------------------------------------------------------
// Scratch (device globals; no runtime allocation allowed)
// ---------------------------------------------------------------------------
__device__ float g_x   [MROWS * EE];
__device__ float g_qkv [MROWS * 3 * EE];
__device__ float g_attn[MROWS * EE];
__device__ float g_ffh [MROWS * FEE * EE];
// transposed weights [N, K] row-major, per layer (tf32-rounded)
__device__ float g_qkvw_t[LL * 3 * EE * EE];
__device__ float g_outw_t[LL * EE * EE];
__device__ float g_ff1w_t[LL * FEE * EE * EE];
__device__ float g_ff2w_t[LL * FEE * EE * EE];

// ---------------------------------------------------------------------------
// PTX helpers (sm_80-era only; target is plain sm_103 — no tcgen05!)
// ---------------------------------------------------------------------------
__device__ __forceinline__ uint32_t smem_u32(const void* p) {
    uint32_t a;
    asm("{ .reg .u64 t; cvta.to.shared.u64 t, %1; cvt.u32.u64 %0, t; }" : "=r"(a) : "l"(p));
    return a;
}

__device__ __forceinline__ float tf32_rn(float x) {
    uint32_t u;
    asm("cvt.rna.tf32.f32 %0, %1;" : "=r"(u) : "f"(x));
    return __uint_as_float(u);
}

#define CP_ASYNC16(dst, src) \
    asm volatile("cp.async.cg.shared.global [%0], [%1], 16;\n" :: "r"(dst), "l"(src))
#define CP_COMMIT() asm volatile("cp.async.commit_group;\n" ::)
#define CP_WAIT1() asm volatile("cp.async.wait_group 1;\n" ::)
#define CP_WAIT0() asm volatile("cp.async.wait_group 0;\n" ::)

#define LDSM_X4(r, addr) \
    asm volatile("ldmatrix.sync.aligned.m8n8.x4.shared.b16 {%0,%1,%2,%3}, [%4];" \
        : "=r"((r)[0]), "=r"((r)[1]), "=r"((r)[2]), "=r"((r)[3]) : "r"(addr))

__device__ __forceinline__ void mma_tf32(float c[4], const uint32_t a[4], const uint32_t b[2]) {
    asm volatile("mma.sync.aligned.m16n8k8.row.col.f32.tf32.tf32.f32 "
        "{%0,%1,%2,%3}, {%4,%5,%6,%7}, {%8,%9}, {%0,%1,%2,%3};"
        : "+f"(c[0]), "+f"(c[1]), "+f"(c[2]), "+f"(c[3])
        : "r"(a[0]), "r"(a[1]), "r"(a[2]), "r"(a[3]), "r"(b[0]), "r"(b[1]));
}

// ---------------------------------------------------------------------------
// Positional encoding
// ---------------------------------------------------------------------------
__global__ void pe_kernel(const float* __restrict__ x, float* __restrict__ out) {
    int idx = blockIdx.x * blockDim.x + threadIdx.x;
    if (idx >= MROWS * EE) return;
    int e = idx & (EE - 1);
    int t = (idx / EE) & (TT - 1);
    int i = (e < 128) ? e : e - 128;
    float f = __expf(-((2.0f * (float)i) * (1.0f / (float)EE)) * 9.210340371976184f);
    float ang = (float)t * f;
    float pe = (e < 128) ? sinf(ang) : cosf(ang);
    out[idx] = x[idx] + pe;
}

// ---------------------------------------------------------------------------
// Weight transpose + tf32 round-to-nearest: in [l][K][N] -> out [l][N][K]
// ---------------------------------------------------------------------------
__global__ void transpose_kernel(const float* __restrict__ in, float* __restrict__ out,
                                 int K, int N) {
    __shared__ float tile[32][33];
    const size_t plane = (size_t)K * N;
    const float* ip = in + blockIdx.z * plane;
    float* op = out + blockIdx.z * plane;
    int n0 = blockIdx.x * 32, k0 = blockIdx.y * 32;
    int tx = threadIdx.x, ty = threadIdx.y;
    #pragma unroll
    for (int i = 0; i < 32; i += 8)
        tile[ty + i][tx] = ip[(size_t)(k0 + ty + i) * N + n0 + tx];
    __syncthreads();
    #pragma unroll
    for (int i = 0; i < 32; i += 8)
        op[(size_t)(n0 + ty + i) * K + k0 + tx] = tf32_rn(tile[tx][ty + i]);
}

// ---------------------------------------------------------------------------
// tf32 mma.sync GEMM: C[M,N] = A[M,K] @ Bt[N,K]^T + bias
// mode bit0 = ReLU, bit1 = tf32-round output.
// Block tile 128x128, BK=32, 8 warps (2m x 4n), 3-stage cp.async pipeline.
// ---------------------------------------------------------------------------
#define GSTAGE 32768           // A (16KB) + B (16KB) per stage
#define GSMEM_TOTAL (3 * GSTAGE)

__device__ __forceinline__ void gemm_load_stage(uint32_t sbase, const float* A, const float* Bt,
                                                int K, int bm, int bn, int kt, int tid) {
    uint32_t abuf = sbase + (uint32_t)(kt % 3) * GSTAGE;
    uint32_t bbuf = abuf + 16384;
    const float* ap = A + (size_t)bm * K + kt * 32;
    const float* bp = Bt + (size_t)bn * K + kt * 32;
    #pragma unroll
    for (int i = 0; i < 4; i++) {
        int f = tid + i * 256;
        int r = f >> 3;
        int cB = (f & 7) * 16;
        uint32_t off = (uint32_t)(r * 128 + cB);
        uint32_t sw = off ^ ((off >> 3) & 0x70);
        CP_ASYNC16(abuf + sw, ap + (size_t)r * K + (cB >> 2));
        CP_ASYNC16(bbuf + sw, bp + (size_t)r * K + (cB >> 2));
    }
    CP_COMMIT();
}

__global__ __launch_bounds__(256)
void gemm_tc_kernel(const float* __restrict__ A, const float* __restrict__ Bt,
                    const float* __restrict__ bias, float* __restrict__ C,
                    int N, int K, int mode) {
    extern __shared__ char smem[];
    uint32_t sbase = smem_u32(smem);
    const int tid = threadIdx.x;
    const int wid = tid >> 5;
    const int lane = tid & 31;
    const int warpM = wid & 1;
    const int warpN = wid >> 1;
    const int bn = blockIdx.x * 128;
    const int bm = blockIdx.y * 128;

    float acc[4][4][4];
    #pragma unroll
    for (int mt = 0; mt < 4; mt++)
        #pragma unroll
        for (int nt = 0; nt < 4; nt++)
            #pragma unroll
            for (int r = 0; r < 4; r++) acc[mt][nt][r] = 0.0f;

    const uint32_t mask = (uint32_t)(lane & 7) << 4;
    uint32_t arowb[4];
    #pragma unroll
    for (int mt = 0; mt < 4; mt++)
        arowb[mt] = (uint32_t)(warpM * 64 + (lane & 15) + mt * 16) * 128;
    const uint32_t achunk = (uint32_t)(lane >> 4) * 16;
    uint32_t browb[2];
    #pragma unroll
    for (int nh = 0; nh < 2; nh++)
        browb[nh] = (uint32_t)(warpN * 32 + nh * 16 + (lane & 7) + ((lane >> 4) << 3)) * 128;
    const uint32_t bchunk = (uint32_t)((lane >> 3) & 1) * 16;

    const int nk = K / 32;
    gemm_load_stage(sbase, A, Bt, K, bm, bn, 0, tid);
    gemm_load_stage(sbase, A, Bt, K, bm, bn, 1, tid);

    for (int kt = 0; kt < nk; kt++) {
        if (kt + 1 < nk) { CP_WAIT1(); } else { CP_WAIT0(); }
        __syncthreads();
        if (kt + 2 < nk) gemm_load_stage(sbase, A, Bt, K, bm, bn, kt + 2, tid);

        const uint32_t ab = sbase + (uint32_t)(kt % 3) * GSTAGE;
        const uint32_t bb = ab + 16384;

        #pragma unroll
        for (int ks = 0; ks < 4; ks++) {
            const uint32_t aco = ((uint32_t)(ks * 32) + achunk) ^ mask;
            const uint32_t bco = ((uint32_t)(ks * 32) + bchunk) ^ mask;

            uint32_t afr[4][4], bfr[2][4];
            #pragma unroll
            for (int mt = 0; mt < 4; mt++) LDSM_X4(afr[mt], ab + arowb[mt] + aco);
            #pragma unroll
            for (int nh = 0; nh < 2; nh++) LDSM_X4(bfr[nh], bb + browb[nh] + bco);

            #pragma unroll
            for (int mt = 0; mt < 4; mt++)
                #pragma unroll
                for (int r = 0; r < 4; r++)
                    afr[mt][r] = __float_as_uint(tf32_rn(__uint_as_float(afr[mt][r])));

            #pragma unroll
            for (int mt = 0; mt < 4; mt++)
                #pragma unroll
                for (int nt = 0; nt < 4; nt++)
                    mma_tf32(acc[mt][nt], afr[mt], &bfr[nt >> 1][(nt & 1) * 2]);
        }
    }

    #pragma unroll
    for (int mt = 0; mt < 4; mt++) {
        const int row0 = bm + warpM * 64 + mt * 16 + (lane >> 2);
        #pragma unroll
        for (int nt = 0; nt < 4; nt++) {
            const int col = bn + warpN * 32 + nt * 8 + (lane & 3) * 2;
            const float2 bi = *(const float2*)&bias[col];
            float v0 = acc[mt][nt][0] + bi.x;
            float v1 = acc[mt][nt][1] + bi.y;
            float v2 = acc[mt][nt][2] + bi.x;
            float v3 = acc[mt][nt][3] + bi.y;
            if (mode & 1) {
                v0 = fmaxf(v0, 0.0f); v1 = fmaxf(v1, 0.0f);
                v2 = fmaxf(v2, 0.0f); v3 = fmaxf(v3, 0.0f);
            }
            if (mode & 2) {
                v0 = tf32_rn(v0); v1 = tf32_rn(v1);
                v2 = tf32_rn(v2); v3 = tf32_rn(v3);
            }
            float2 p0; p0.x = v0; p0.y = v1;
            float2 p1; p1.x = v2; p1.y = v3;
            *(float2*)&C[(size_t)row0 * N + col] = p0;
            *(float2*)&C[(size_t)(row0 + 8) * N + col] = p1;
        }
    }
}

// ---------------------------------------------------------------------------
// Fused GEMM (N=256) + bias + residual + LayerNorm:
//   out = LN(res + A @ Bt^T + bias) * g + beta
// BM=64, BN=256, 8 warps (2m x 4n). A inputs are pre-rounded tf32.
// ---------------------------------------------------------------------------
#define LSTAGE 40960           // A (8KB) + B (32KB)
#define LSMEM_TOTAL (3 * LSTAGE)

__device__ __forceinline__ void gemmln_load_stage(uint32_t sbase, const float* A, const float* Bt,
                                                  int K, int bm, int kt, int tid) {
    uint32_t abuf = sbase + (uint32_t)(kt % 3) * LSTAGE;
    uint32_t bbuf = abuf + 8192;
    const float* ap = A + (size_t)bm * K + kt * 32;
    const float* bp = Bt + kt * 32;
    #pragma unroll
    for (int i = 0; i < 2; i++) {
        int f = tid + i * 256;
        int r = f >> 3;
        int cB = (f & 7) * 16;
        uint32_t off = (uint32_t)(r * 128 + cB);
        uint32_t sw = off ^ ((off >> 3) & 0x70);
        CP_ASYNC16(abuf + sw, ap + (size_t)r * K + (cB >> 2));
    }
    #pragma unroll
    for (int i = 0; i < 8; i++) {
        int f = tid + i * 256;
        int r = f >> 3;
        int cB = (f & 7) * 16;
        uint32_t off = (uint32_t)(r * 128 + cB);
        uint32_t sw = off ^ ((off >> 3) & 0x70);
        CP_ASYNC16(bbuf + sw, bp + (size_t)r * K + (cB >> 2));
    }
    CP_COMMIT();
}

__global__ __launch_bounds__(256)
void gemm_ln_kernel(const float* __restrict__ A, const float* __restrict__ Bt,
                    const float* __restrict__ bias, const float* __restrict__ res,
                    const float* __restrict__ g, const float* __restrict__ beta,
                    float* __restrict__ out, int K) {
    extern __shared__ char smem[];
    uint32_t sbase = smem_u32(smem);
    const int tid = threadIdx.x;
    const int wid = tid >> 5;
    const int lane = tid & 31;
    const int warpM = wid & 1;
    const int warpN = wid >> 1;
    const int bm = blockIdx.x * 64;

    float acc[2][8][4];
    #pragma unroll
    for (int mt = 0; mt < 2; mt++)
        #pragma unroll
        for (int nt = 0; nt < 8; nt++)
            #pragma unroll
            for (int r = 0; r < 4; r++) acc[mt][nt][r] = 0.0f;

    const uint32_t mask = (uint32_t)(lane & 7) << 4;
    uint32_t arowb[2];
    #pragma unroll
    for (int mt = 0; mt < 2; mt++)
        arowb[mt] = (uint32_t)(warpM * 32 + mt * 16 + (lane & 15)) * 128;
    const uint32_t achunk = (uint32_t)(lane >> 4) * 16;
    uint32_t browb[4];
    #pragma unroll
    for (int nh = 0; nh < 4; nh++)
        browb[nh] = (uint32_t)(warpN * 64 + nh * 16 + (lane & 7) + ((lane >> 4) << 3)) * 128;
    const uint32_t bchunk = (uint32_t)((lane >> 3) & 1) * 16;

    const int nk = K / 32;
    gemmln_load_stage(sbase, A, Bt, K, bm, 0, tid);
    gemmln_load_stage(sbase, A, Bt, K, bm, 1, tid);

    for (int kt = 0; kt < nk; kt++) {
        if (kt + 1 < nk) { CP_WAIT1(); } else { CP_WAIT0(); }
        __syncthreads();
        if (kt + 2 < nk) gemmln_load_stage(sbase, A, Bt, K, bm, kt + 2, tid);

        const uint32_t ab = sbase + (uint32_t)(kt % 3) * LSTAGE;
        const uint32_t bb = ab + 8192;

        #pragma unroll
        for (int ks = 0; ks < 4; ks++) {
            const uint32_t aco = ((uint32_t)(ks * 32) + achunk) ^ mask;
            const uint32_t bco = ((uint32_t)(ks * 32) + bchunk) ^ mask;

            uint32_t afr[2][4], bfr[4][4];
            #pragma unroll
            for (int mt = 0; mt < 2; mt++) LDSM_X4(afr[mt], ab + arowb[mt] + aco);
            #pragma unroll
            for (int nh = 0; nh < 4; nh++) LDSM_X4(bfr[nh], bb + browb[nh] + bco);

            #pragma unroll
            for (int mt = 0; mt < 2; mt++)
                #pragma unroll
                for (int nt = 0; nt < 8; nt++)
                    mma_tf32(acc[mt][nt], afr[mt], &bfr[nt >> 1][(nt & 1) * 2]);
        }
    }
    __syncthreads();   // smem free for reductions now

    float* redS = (float*)smem;           // [64][4]
    float* redQ = (float*)smem + 256;     // [64][4]

    const int rl = lane >> 2;
    const int cl = (lane & 3) * 2;
    float sum[2][2] = {{0,0},{0,0}}, sq[2][2] = {{0,0},{0,0}};

    #pragma unroll
    for (int mt = 0; mt < 2; mt++) {
        const int rlo = bm + warpM * 32 + mt * 16 + rl;
        #pragma unroll
        for (int nt = 0; nt < 8; nt++) {
            const int col = warpN * 64 + nt * 8 + cl;
            const float2 bi = *(const float2*)&bias[col];
            const float2 r0 = *(const float2*)&res[(size_t)rlo * EE + col];
            const float2 r1 = *(const float2*)&res[(size_t)(rlo + 8) * EE + col];
            float v0 = acc[mt][nt][0] + bi.x + r0.x;
            float v1 = acc[mt][nt][1] + bi.y + r0.y;
            float v2 = acc[mt][nt][2] + bi.x + r1.x;
            float v3 = acc[mt][nt][3] + bi.y + r1.y;
            acc[mt][nt][0] = v0; acc[mt][nt][1] = v1;
            acc[mt][nt][2] = v2; acc[mt][nt][3] = v3;
            sum[mt][0] += v0 + v1;     sum[mt][1] += v2 + v3;
            sq[mt][0]  += v0*v0 + v1*v1; sq[mt][1] += v2*v2 + v3*v3;
        }
    }
    #pragma unroll
    for (int mt = 0; mt < 2; mt++)
        #pragma unroll
        for (int hh = 0; hh < 2; hh++) {
            sum[mt][hh] += __shfl_xor_sync(0xffffffffu, sum[mt][hh], 1);
            sum[mt][hh] += __shfl_xor_sync(0xffffffffu, sum[mt][hh], 2);
            sq[mt][hh]  += __shfl_xor_sync(0xffffffffu, sq[mt][hh], 1);
            sq[mt][hh]  += __shfl_xor_sync(0xffffffffu, sq[mt][hh], 2);
        }
    if ((lane & 3) == 0) {
        #pragma unroll
        for (int mt = 0; mt < 2; mt++) {
            int rloc = warpM * 32 + mt * 16 + rl;
            redS[rloc * 4 + warpN] = sum[mt][0];
            redQ[rloc * 4 + warpN] = sq[mt][0];
            redS[(rloc + 8) * 4 + warpN] = sum[mt][1];
            redQ[(rloc + 8) * 4 + warpN] = sq[mt][1];
        }
    }
    __syncthreads();

    #pragma unroll
    for (int mt = 0; mt < 2; mt++) {
        #pragma unroll
        for (int hh = 0; hh < 2; hh++) {
            const int rloc = warpM * 32 + mt * 16 + rl + hh * 8;
            float ts = redS[rloc * 4 + 0] + redS[rloc * 4 + 1]
                     + redS[rloc * 4 + 2] + redS[rloc * 4 + 3];
            float tq = redQ[rloc * 4 + 0] + redQ[rloc * 4 + 1]
                     + redQ[rloc * 4 + 2] + redQ[rloc * 4 + 3];
            const float mu = ts * (1.0f / (float)EE);
            const float var = tq * (1.0f / (float)EE) - mu * mu;
            const float inv = rsqrtf(var + EPS);
            const int row = bm + rloc;
            #pragma unroll
            for (int nt = 0; nt < 8; nt++) {
                const int col = warpN * 64 + nt * 8 + cl;
                const float2 gg = *(const float2*)&g[col];
                const float2 bb = *(const float2*)&beta[col];
                float v0 = acc[mt][nt][2 * hh + 0];
                float v1 = acc[mt][nt][2 * hh + 1];
                float2 o;
                o.x = (v0 - mu) * inv * gg.x + bb.x;
                o.y = (v1 - mu) * inv * gg.y + bb.y;
                *(float2*)&out[(size_t)row * EE + col] = o;
            }
        }
    }
}

// ---------------------------------------------------------------------------
// Tensor-core flash attention (tf32 mma.sync) with cp.async KV pipeline.
// Block = (b,h) x 128-query tile; 8 warps x 16 rows. KV tiles of 64 keys,
// 3-stage cp.async. qkv values are pre-rounded to tf32 by the QKV GEMM.
// qkv layout: [B,T,H,3,HD] -> (b*T+t)*768 + h*96 + s*32 + d
// ---------------------------------------------------------------------------
#define AST_K 8192                      // 64 keys x 128B (swizzled)
#define AST_V 10240                     // 64 keys x 40 floats
#define ASTAGE (AST_K + AST_V)          // 18432
#define APOFF (3 * ASTAGE)              // 55296: P buffers
#define PWARP (16 * 68 * 4)             // 4352 bytes per warp
#define ASMEM_TOTAL (APOFF + 8 * PWARP) // 90112

__device__ __forceinline__ void attn_load_kv(uint32_t sbase, const float* kv0,
                                             int kt, int tid) {
    uint32_t kbuf = sbase + (uint32_t)(kt % 3) * ASTAGE;
    uint32_t vbuf = kbuf + AST_K;
    const float* src0 = kv0 + (size_t)(kt * 64) * 768;
    #pragma unroll
    for (int i = 0; i < 2; i++) {
        int f = tid + i * 256;           // 0..511
        int j = f >> 3;                  // key 0..63
        int c = f & 7;                   // 16B chunk
        const float* s = src0 + (size_t)j * 768 + 32 + c * 4;   // K slot
        uint32_t koff = (uint32_t)(j * 128 + c * 16);
        CP_ASYNC16(kbuf + (koff ^ ((koff >> 3) & 0x70)), s);
        CP_ASYNC16(vbuf + (uint32_t)(j * 160 + c * 16), s + 32); // V slot
    }
    CP_COMMIT();
}

__global__ __launch_bounds__(256)
void attn_tc_kernel(const float* __restrict__ qkv, float* __restrict__ out) {
    extern __shared__ char smem[];
    uint32_t sbase = smem_u32(smem);

    const int tid = threadIdx.x;
    const int wid = tid >> 5;
    const int lane = tid & 31;
    const int qt = blockIdx.x;               // 0..15 (128 queries each)
    const int bh = blockIdx.y;               // 0..31
    const int h = bh & (HH - 1);
    const int b = bh >> 3;

    const float scale = 0.17677669529663687f;   // 1/sqrt(32)

    // --- Q fragments (A, m16k8 x 4 ksteps), pre-scaled + tf32 RN rounded ---
    uint32_t qfr[4][4];
    {
        const int r_lo = qt * 128 + wid * 16 + (lane >> 2);
        const size_t base_lo = (size_t)(b * TT + r_lo) * 768 + h * 96;
        const size_t base_hi = base_lo + 8 * 768;
        #pragma unroll
        for (int ks = 0; ks < 4; ks++) {
            int c0 = ks * 8 + (lane & 3);
            qfr[ks][0] = __float_as_uint(tf32_rn(qkv[base_lo + c0] * scale));
            qfr[ks][1] = __float_as_uint(tf32_rn(qkv[base_hi + c0] * scale));
            qfr[ks][2] = __float_as_uint(tf32_rn(qkv[base_lo + c0 + 4] * scale));
            qfr[ks][3] = __float_as_uint(tf32_rn(qkv[base_hi + c0 + 4] * scale));
        }
    }

    float ofr[4][4];
    #pragma unroll
    for (int nd = 0; nd < 4; nd++)
        #pragma unroll
        for (int r = 0; r < 4; r++) ofr[nd][r] = 0.0f;
    float m_lo = -INFINITY, m_hi = -INFINITY, l_lo = 0.0f, l_hi = 0.0f;

    // K ldmatrix addressing (B fragments over 64 keys)
    const uint32_t mask = (uint32_t)(lane & 7) << 4;
    const uint32_t krow = (uint32_t)((lane & 7) + ((lane >> 4) << 3)) * 128;
    const uint32_t kchunk = (uint32_t)((lane >> 3) & 1) * 16;

    // P buffers
    float* Pw = (float*)(smem + APOFF + wid * PWARP);
    const uint32_t pldsm = sbase + APOFF + (uint32_t)(wid * PWARP)
                         + (uint32_t)((lane & 15) * 272) + ((uint32_t)(lane >> 4) << 4);

    const float* kv0 = qkv + (size_t)(b * TT) * 768 + h * 96;

    attn_load_kv(sbase, kv0, 0, tid);
    attn_load_kv(sbase, kv0, 1, tid);

    const int nk = TT / 64;
    for (int kt = 0; kt < nk; kt++) {
        if (kt + 1 < nk) { CP_WAIT1(); } else { CP_WAIT0(); }
        __syncthreads();
        if (kt + 2 < nk) attn_load_kv(sbase, kv0, kt + 2, tid);

        const uint32_t kb = sbase + (uint32_t)(kt % 3) * ASTAGE;
        const uint32_t* Vsu = (const uint32_t*)(smem + (kt % 3) * ASTAGE + AST_K);

        // --- S = Q K^T ---
        float sfr[8][4];
        #pragma unroll
        for (int nt = 0; nt < 8; nt++)
            #pragma unroll
            for (int r = 0; r < 4; r++) sfr[nt][r] = 0.0f;

        #pragma unroll
        for (int ks = 0; ks < 4; ks++) {
            const uint32_t co = ((uint32_t)(ks * 32) + kchunk) ^ mask;
            uint32_t kfr[4][4];
            #pragma unroll
            for (int gI = 0; gI < 4; gI++)
                LDSM_X4(kfr[gI], kb + (uint32_t)(gI * 16 * 128) + krow + co);
            #pragma unroll
            for (int nt = 0; nt < 8; nt++)
                mma_tf32(sfr[nt], qfr[ks], &kfr[nt >> 1][(nt & 1) * 2]);
        }

        // --- online softmax ---
        float mx_lo = sfr[0][0], mx_hi = sfr[0][2];
        #pragma unroll
        for (int nt = 0; nt < 8; nt++) {
            mx_lo = fmaxf(mx_lo, fmaxf(sfr[nt][0], sfr[nt][1]));
            mx_hi = fmaxf(mx_hi, fmaxf(sfr[nt][2], sfr[nt][3]));
        }
        mx_lo = fmaxf(mx_lo, __shfl_xor_sync(0xffffffffu, mx_lo, 1));
        mx_lo = fmaxf(mx_lo, __shfl_xor_sync(0xffffffffu, mx_lo, 2));
        mx_hi = fmaxf(mx_hi, __shfl_xor_sync(0xffffffffu, mx_hi, 1));
        mx_hi = fmaxf(mx_hi, __shfl_xor_sync(0xffffffffu, mx_hi, 2));

        const float nm_lo = fmaxf(m_lo, mx_lo);
        const float nm_hi = fmaxf(m_hi, mx_hi);
        const float corr_lo = __expf(m_lo - nm_lo);   // exp(-inf)=0 first tile
        const float corr_hi = __expf(m_hi - nm_hi);
        m_lo = nm_lo; m_hi = nm_hi;

        float ps_lo = 0.0f, ps_hi = 0.0f;
        {
            const int rl = (lane >> 2);
            const int cb = 2 * (lane & 3);
            float* prow_lo = Pw + rl * 68 + cb;
            float* prow_hi = Pw + (rl + 8) * 68 + cb;
            #pragma unroll
            for (int nt = 0; nt < 8; nt++) {
                float p0 = __expf(sfr[nt][0] - m_lo);
                float p1 = __expf(sfr[nt][1] - m_lo);
                float p2 = __expf(sfr[nt][2] - m_hi);
                float p3 = __expf(sfr[nt][3] - m_hi);
                ps_lo += p0 + p1;
                ps_hi += p2 + p3;
                float2 w0; w0.x = tf32_rn(p0); w0.y = tf32_rn(p1);
                float2 w1; w1.x = tf32_rn(p2); w1.y = tf32_rn(p3);
                *(float2*)(prow_lo + nt * 8) = w0;
                *(float2*)(prow_hi + nt * 8) = w1;
            }
        }
        l_lo = l_lo * corr_lo + ps_lo;
        l_hi = l_hi * corr_hi + ps_hi;
        #pragma unroll
        for (int nd = 0; nd < 4; nd++) {
            ofr[nd][0] *= corr_lo; ofr[nd][1] *= corr_lo;
            ofr[nd][2] *= corr_hi; ofr[nd][3] *= corr_hi;
        }
        __syncwarp();

        // --- O += P V : P via ldmatrix, V scalar (conflict-free pad 40) ---
        {
            const int rl = (lane >> 2);
            const int cl = (lane & 3);
            #pragma unroll
            for (int kk = 0; kk < 8; kk++) {
                uint32_t afr[4];
                LDSM_X4(afr, pldsm + (uint32_t)(kk * 32));
                #pragma unroll
                for (int nd = 0; nd < 4; nd++) {
                    uint32_t bfr[2];
                    bfr[0] = Vsu[(kk * 8 + cl) * 40 + nd * 8 + rl];
                    bfr[1] = Vsu[(kk * 8 + cl + 4) * 40 + nd * 8 + rl];
                    mma_tf32(ofr[nd], afr, bfr);
                }
            }
        }
        __syncwarp();
    }

    // final l reduction across quad + store (tf32-rounded for next GEMM)
    l_lo += __shfl_xor_sync(0xffffffffu, l_lo, 1);
    l_lo += __shfl_xor_sync(0xffffffffu, l_lo, 2);
    l_hi += __shfl_xor_sync(0xffffffffu, l_hi, 1);
    l_hi += __shfl_xor_sync(0xffffffffu, l_hi, 2);
    const float inv_lo = 1.0f / l_lo;
    const float inv_hi = 1.0f / l_hi;

    const int t_lo = qt * 128 + wid * 16 + (lane >> 2);
    const size_t ob_lo = (size_t)(b * TT + t_lo) * EE + h * HD + 2 * (lane & 3);
    const size_t ob_hi = ob_lo + 8 * EE;
    #pragma unroll
    for (int nd = 0; nd < 4; nd++) {
        float2 v0; v0.x = tf32_rn(ofr[nd][0] * inv_lo); v0.y = tf32_rn(ofr[nd][1] * inv_lo);
        float2 v1; v1.x = tf32_rn(ofr[nd][2] * inv_hi); v1.y = tf32_rn(ofr[nd][3] * inv_hi);
        *(float2*)&out[ob_lo + nd * 8] = v0;
        *(float2*)&out[ob_hi + nd * 8] = v1;
    }
}

// ---------------------------------------------------------------------------
// kernel_launch
// ---------------------------------------------------------------------------
extern "C" void kernel_launch(void* const* d_in, const int* in_sizes, int n_in,
                              void* d_out, int out_size) {
    const float* x     = (const float*)d_in[0];
    const float* qkv_w = (const float*)d_in[1];
    const float* qkv_b = (const float*)d_in[2];
    const float* out_w = (const float*)d_in[3];
    const float* out_b = (const float*)d_in[4];
    const float* ff1_w = (const float*)d_in[5];
    const float* ff1_b = (const float*)d_in[6];
    const float* ff2_w = (const float*)d_in[7];
    const float* ff2_b = (const float*)d_in[8];
    const float* ln1_g = (const float*)d_in[9];
    const float* ln1_b = (const float*)d_in[10];
    const float* ln2_g = (const float*)d_in[11];
    const float* ln2_b = (const float*)d_in[12];
    float* outp = (float*)d_out;

    float *gx, *gqkv, *gattn, *gffh, *wq, *wo, *w1, *w2;
    cudaGetSymbolAddress((void**)&gx,   g_x);
    cudaGetSymbolAddress((void**)&gqkv, g_qkv);
    cudaGetSymbolAddress((void**)&gattn,g_attn);
    cudaGetSymbolAddress((void**)&gffh, g_ffh);
    cudaGetSymbolAddress((void**)&wq,   g_qkvw_t);
    cudaGetSymbolAddress((void**)&wo,   g_outw_t);
    cudaGetSymbolAddress((void**)&w1,   g_ff1w_t);
    cudaGetSymbolAddress((void**)&w2,   g_ff2w_t);

    cudaFuncSetAttribute(gemm_tc_kernel, cudaFuncAttributeMaxDynamicSharedMemorySize, GSMEM_TOTAL);
    cudaFuncSetAttribute(gemm_ln_kernel, cudaFuncAttributeMaxDynamicSharedMemorySize, LSMEM_TOTAL);
    cudaFuncSetAttribute(attn_tc_kernel, cudaFuncAttributeMaxDynamicSharedMemorySize, ASMEM_TOTAL);

    const dim3 tthr(32, 8);
    transpose_kernel<<<dim3(24, 8, LL), tthr>>>(qkv_w, wq, EE, 3 * EE);
    transpose_kernel<<<dim3(8, 8, LL), tthr>>>(out_w, wo, EE, EE);
    transpose_kernel<<<dim3(32, 8, LL), tthr>>>(ff1_w, w1, EE, FEE * EE);
    transpose_kernel<<<dim3(8, 32, LL), tthr>>>(ff2_w, w2, FEE * EE, EE);

    pe_kernel<<<(MROWS * EE + 255) / 256, 256>>>(x, gx);

    for (int i = 0; i < LL; i++) {
        // qkv = x @ qkv_w + b    (8192 x 768, K=256)  -> tf32-rounded output
        gemm_tc_kernel<<<dim3(6, 64), 256, GSMEM_TOTAL>>>(
            gx, wq + (size_t)i * 3 * EE * EE, qkv_b + (size_t)i * 3 * EE,
            gqkv, 3 * EE, EE, 2);

        // tensor-core flash attention (output tf32-rounded)
        attn_tc_kernel<<<dim3(TT / 128, BB * HH), 256, ASMEM_TOTAL>>>(gqkv, gattn);

        // x = LN(x + attn @ out_w + out_b)    (fused)
        gemm_ln_kernel<<<MROWS / 64, 256, LSMEM_TOTAL>>>(
            gattn, wo + (size_t)i * EE * EE, out_b + (size_t)i * EE,
            gx, ln1_g + (size_t)i * EE, ln1_b + (size_t)i * EE, gx, EE);

        // h = relu(x @ ff1_w + b)  (8192 x 1024, K=256) -> relu + tf32-rounded
        gemm_tc_kernel<<<dim3(8, 64), 256, GSMEM_TOTAL>>>(
            gx, w1 + (size_t)i * FEE * EE * EE, ff1_b + (size_t)i * FEE * EE,
            gffh, FEE * EE, EE, 3);

        // x = LN(x + h @ ff2_w + ff2_b)       (fused; K=1024)
        float* dst = (i == LL - 1) ? outp : gx;
        gemm_ln_kernel<<<MROWS / 64, 256, LSMEM_TOTAL>>>(
            gffh, w2 + (size_t)i * FEE * EE * EE, ff2_b + (size_t)i * EE,
            gx, ln2_g + (size_t)i * EE, ln2_b + (size_t)i * EE, dst, FEE * EE);
    }
}

// round 9
// speedup vs baseline: 6.0128x; 1.0255x over previous
#include <cuda_runtime.h>
#include <cuda_bf16.h>
#include <math.h>
#include <cstdint>

// Problem constants
#define BB 4
#define TT 2048
#define EE 256
#define HH 8
#define HD 32
#define FEE 4
#define LL 4
#define MROWS (BB*TT)          // 8192
#define EPS 1e-5f

// ---------------------------------------------------------------------------
// Scratch (device globals; no runtime allocation allowed)
// ---------------------------------------------------------------------------
__device__ float g_x   [MROWS * EE];
__device__ float g_qkv [MROWS * 3 * EE];
__device__ float g_attn[MROWS * EE];
__device__ float g_ffh [MROWS * FEE * EE];
// transposed weights [N, K] row-major, per layer (tf32-rounded)
__device__ float g_qkvw_t[LL * 3 * EE * EE];
__device__ float g_outw_t[LL * EE * EE];
__device__ float g_ff1w_t[LL * FEE * EE * EE];
__device__ float g_ff2w_t[LL * FEE * EE * EE];

// ---------------------------------------------------------------------------
// PTX helpers (sm_80-era only; target is plain sm_103 — no tcgen05!)
// ---------------------------------------------------------------------------
__device__ __forceinline__ uint32_t smem_u32(const void* p) {
    uint32_t a;
    asm("{ .reg .u64 t; cvta.to.shared.u64 t, %1; cvt.u32.u64 %0, t; }" : "=r"(a) : "l"(p));
    return a;
}

__device__ __forceinline__ float tf32_rn(float x) {
    uint32_t u;
    asm("cvt.rna.tf32.f32 %0, %1;" : "=r"(u) : "f"(x));
    return __uint_as_float(u);
}

#define CP_ASYNC16(dst, src) \
    asm volatile("cp.async.cg.shared.global [%0], [%1], 16;\n" :: "r"(dst), "l"(src))
#define CP_COMMIT() asm volatile("cp.async.commit_group;\n" ::)
#define CP_WAIT1() asm volatile("cp.async.wait_group 1;\n" ::)
#define CP_WAIT0() asm volatile("cp.async.wait_group 0;\n" ::)

#define LDSM_X4(r, addr) \
    asm volatile("ldmatrix.sync.aligned.m8n8.x4.shared.b16 {%0,%1,%2,%3}, [%4];" \
        : "=r"((r)[0]), "=r"((r)[1]), "=r"((r)[2]), "=r"((r)[3]) : "r"(addr))

__device__ __forceinline__ void mma_tf32(float c[4], const uint32_t a[4], const uint32_t b[2]) {
    asm volatile("mma.sync.aligned.m16n8k8.row.col.f32.tf32.tf32.f32 "
        "{%0,%1,%2,%3}, {%4,%5,%6,%7}, {%8,%9}, {%0,%1,%2,%3};"
        : "+f"(c[0]), "+f"(c[1]), "+f"(c[2]), "+f"(c[3])
        : "r"(a[0]), "r"(a[1]), "r"(a[2]), "r"(a[3]), "r"(b[0]), "r"(b[1]));
}

// ---------------------------------------------------------------------------
// Positional encoding (output tf32-rounded: it feeds GEMM A operands)
// ---------------------------------------------------------------------------
__global__ void pe_kernel(const float* __restrict__ x, float* __restrict__ out) {
    int idx = blockIdx.x * blockDim.x + threadIdx.x;
    if (idx >= MROWS * EE) return;
    int e = idx & (EE - 1);
    int t = (idx / EE) & (TT - 1);
    int i = (e < 128) ? e : e - 128;
    float f = __expf(-((2.0f * (float)i) * (1.0f / (float)EE)) * 9.210340371976184f);
    float ang = (float)t * f;
    float pe = (e < 128) ? sinf(ang) : cosf(ang);
    out[idx] = tf32_rn(x[idx] + pe);
}

// ---------------------------------------------------------------------------
// Weight transpose + tf32 round-to-nearest: in [l][K][N] -> out [l][N][K]
// ---------------------------------------------------------------------------
__global__ void transpose_kernel(const float* __restrict__ in, float* __restrict__ out,
                                 int K, int N) {
    __shared__ float tile[32][33];
    const size_t plane = (size_t)K * N;
    const float* ip = in + blockIdx.z * plane;
    float* op = out + blockIdx.z * plane;
    int n0 = blockIdx.x * 32, k0 = blockIdx.y * 32;
    int tx = threadIdx.x, ty = threadIdx.y;
    #pragma unroll
    for (int i = 0; i < 32; i += 8)
        tile[ty + i][tx] = ip[(size_t)(k0 + ty + i) * N + n0 + tx];
    __syncthreads();
    #pragma unroll
    for (int i = 0; i < 32; i += 8)
        op[(size_t)(n0 + ty + i) * K + k0 + tx] = tf32_rn(tile[tx][ty + i]);
}

// ---------------------------------------------------------------------------
// tf32 mma.sync GEMM: C[M,N] = A[M,K] @ Bt[N,K]^T + bias
// A and Bt are PRE-ROUNDED tf32 (no in-loop cvt). mode bit0=ReLU, bit1=round out.
// Block tile 128x128, BK=32, 8 warps (2m x 4n), 3-stage cp.async pipeline.
// ---------------------------------------------------------------------------
#define GSTAGE 32768           // A (16KB) + B (16KB) per stage
#define GSMEM_TOTAL (3 * GSTAGE)

__device__ __forceinline__ void gemm_load_stage(uint32_t sbase, const float* A, const float* Bt,
                                                int K, int bm, int bn, int kt, int tid) {
    uint32_t abuf = sbase + (uint32_t)(kt % 3) * GSTAGE;
    uint32_t bbuf = abuf + 16384;
    const float* ap = A + (size_t)bm * K + kt * 32;
    const float* bp = Bt + (size_t)bn * K + kt * 32;
    #pragma unroll
    for (int i = 0; i < 4; i++) {
        int f = tid + i * 256;
        int r = f >> 3;
        int cB = (f & 7) * 16;
        uint32_t off = (uint32_t)(r * 128 + cB);
        uint32_t sw = off ^ ((off >> 3) & 0x70);
        CP_ASYNC16(abuf + sw, ap + (size_t)r * K + (cB >> 2));
        CP_ASYNC16(bbuf + sw, bp + (size_t)r * K + (cB >> 2));
    }
    CP_COMMIT();
}

__global__ __launch_bounds__(256)
void gemm_tc_kernel(const float* __restrict__ A, const float* __restrict__ Bt,
                    const float* __restrict__ bias, float* __restrict__ C,
                    int N, int K, int mode) {
    extern __shared__ char smem[];
    uint32_t sbase = smem_u32(smem);
    const int tid = threadIdx.x;
    const int wid = tid >> 5;
    const int lane = tid & 31;
    const int warpM = wid & 1;
    const int warpN = wid >> 1;
    const int bn = blockIdx.x * 128;
    const int bm = blockIdx.y * 128;

    float acc[4][4][4];
    #pragma unroll
    for (int mt = 0; mt < 4; mt++)
        #pragma unroll
        for (int nt = 0; nt < 4; nt++)
            #pragma unroll
            for (int r = 0; r < 4; r++) acc[mt][nt][r] = 0.0f;

    const uint32_t mask = (uint32_t)(lane & 7) << 4;
    uint32_t arowb[4];
    #pragma unroll
    for (int mt = 0; mt < 4; mt++)
        arowb[mt] = (uint32_t)(warpM * 64 + (lane & 15) + mt * 16) * 128;
    const uint32_t achunk = (uint32_t)(lane >> 4) * 16;
    uint32_t browb[2];
    #pragma unroll
    for (int nh = 0; nh < 2; nh++)
        browb[nh] = (uint32_t)(warpN * 32 + nh * 16 + (lane & 7) + ((lane >> 4) << 3)) * 128;
    const uint32_t bchunk = (uint32_t)((lane >> 3) & 1) * 16;

    const int nk = K / 32;
    gemm_load_stage(sbase, A, Bt, K, bm, bn, 0, tid);
    gemm_load_stage(sbase, A, Bt, K, bm, bn, 1, tid);

    for (int kt = 0; kt < nk; kt++) {
        if (kt + 1 < nk) { CP_WAIT1(); } else { CP_WAIT0(); }
        __syncthreads();
        if (kt + 2 < nk) gemm_load_stage(sbase, A, Bt, K, bm, bn, kt + 2, tid);

        const uint32_t ab = sbase + (uint32_t)(kt % 3) * GSTAGE;
        const uint32_t bb = ab + 16384;

        #pragma unroll
        for (int ks = 0; ks < 4; ks++) {
            const uint32_t aco = ((uint32_t)(ks * 32) + achunk) ^ mask;
            const uint32_t bco = ((uint32_t)(ks * 32) + bchunk) ^ mask;

            uint32_t afr[4][4], bfr[2][4];
            #pragma unroll
            for (int mt = 0; mt < 4; mt++) LDSM_X4(afr[mt], ab + arowb[mt] + aco);
            #pragma unroll
            for (int nh = 0; nh < 2; nh++) LDSM_X4(bfr[nh], bb + browb[nh] + bco);

            #pragma unroll
            for (int mt = 0; mt < 4; mt++)
                #pragma unroll
                for (int nt = 0; nt < 4; nt++)
                    mma_tf32(acc[mt][nt], afr[mt], &bfr[nt >> 1][(nt & 1) * 2]);
        }
    }

    #pragma unroll
    for (int mt = 0; mt < 4; mt++) {
        const int row0 = bm + warpM * 64 + mt * 16 + (lane >> 2);
        #pragma unroll
        for (int nt = 0; nt < 4; nt++) {
            const int col = bn + warpN * 32 + nt * 8 + (lane & 3) * 2;
            const float2 bi = *(const float2*)&bias[col];
            float v0 = acc[mt][nt][0] + bi.x;
            float v1 = acc[mt][nt][1] + bi.y;
            float v2 = acc[mt][nt][2] + bi.x;
            float v3 = acc[mt][nt][3] + bi.y;
            if (mode & 1) {
                v0 = fmaxf(v0, 0.0f); v1 = fmaxf(v1, 0.0f);
                v2 = fmaxf(v2, 0.0f); v3 = fmaxf(v3, 0.0f);
            }
            if (mode & 2) {
                v0 = tf32_rn(v0); v1 = tf32_rn(v1);
                v2 = tf32_rn(v2); v3 = tf32_rn(v3);
            }
            float2 p0; p0.x = v0; p0.y = v1;
            float2 p1; p1.x = v2; p1.y = v3;
            *(float2*)&C[(size_t)row0 * N + col] = p0;
            *(float2*)&C[(size_t)(row0 + 8) * N + col] = p1;
        }
    }
}

// ---------------------------------------------------------------------------
// Fused GEMM (N=256) + bias + residual + LayerNorm:
//   out = LN(res + A @ Bt^T + bias) * g + beta   [optionally tf32-rounded]
// BM=64, BN=256, 8 warps (2m x 4n). A inputs are pre-rounded tf32.
// ---------------------------------------------------------------------------
#define LSTAGE 40960           // A (8KB) + B (32KB)
#define LSMEM_TOTAL (3 * LSTAGE)

__device__ __forceinline__ void gemmln_load_stage(uint32_t sbase, const float* A, const float* Bt,
                                                  int K, int bm, int kt, int tid) {
    uint32_t abuf = sbase + (uint32_t)(kt % 3) * LSTAGE;
    uint32_t bbuf = abuf + 8192;
    const float* ap = A + (size_t)bm * K + kt * 32;
    const float* bp = Bt + kt * 32;
    #pragma unroll
    for (int i = 0; i < 2; i++) {
        int f = tid + i * 256;
        int r = f >> 3;
        int cB = (f & 7) * 16;
        uint32_t off = (uint32_t)(r * 128 + cB);
        uint32_t sw = off ^ ((off >> 3) & 0x70);
        CP_ASYNC16(abuf + sw, ap + (size_t)r * K + (cB >> 2));
    }
    #pragma unroll
    for (int i = 0; i < 8; i++) {
        int f = tid + i * 256;
        int r = f >> 3;
        int cB = (f & 7) * 16;
        uint32_t off = (uint32_t)(r * 128 + cB);
        uint32_t sw = off ^ ((off >> 3) & 0x70);
        CP_ASYNC16(bbuf + sw, bp + (size_t)r * K + (cB >> 2));
    }
    CP_COMMIT();
}

__global__ __launch_bounds__(256)
void gemm_ln_kernel(const float* __restrict__ A, const float* __restrict__ Bt,
                    const float* __restrict__ bias, const float* __restrict__ res,
                    const float* __restrict__ g, const float* __restrict__ beta,
                    float* __restrict__ out, int K, int roundOut) {
    extern __shared__ char smem[];
    uint32_t sbase = smem_u32(smem);
    const int tid = threadIdx.x;
    const int wid = tid >> 5;
    const int lane = tid & 31;
    const int warpM = wid & 1;
    const int warpN = wid >> 1;
    const int bm = blockIdx.x * 64;

    float acc[2][8][4];
    #pragma unroll
    for (int mt = 0; mt < 2; mt++)
        #pragma unroll
        for (int nt = 0; nt < 8; nt++)
            #pragma unroll
            for (int r = 0; r < 4; r++) acc[mt][nt][r] = 0.0f;

    const uint32_t mask = (uint32_t)(lane & 7) << 4;
    uint32_t arowb[2];
    #pragma unroll
    for (int mt = 0; mt < 2; mt++)
        arowb[mt] = (uint32_t)(warpM * 32 + mt * 16 + (lane & 15)) * 128;
    const uint32_t achunk = (uint32_t)(lane >> 4) * 16;
    uint32_t browb[4];
    #pragma unroll
    for (int nh = 0; nh < 4; nh++)
        browb[nh] = (uint32_t)(warpN * 64 + nh * 16 + (lane & 7) + ((lane >> 4) << 3)) * 128;
    const uint32_t bchunk = (uint32_t)((lane >> 3) & 1) * 16;

    const int nk = K / 32;
    gemmln_load_stage(sbase, A, Bt, K, bm, 0, tid);
    gemmln_load_stage(sbase, A, Bt, K, bm, 1, tid);

    for (int kt = 0; kt < nk; kt++) {
        if (kt + 1 < nk) { CP_WAIT1(); } else { CP_WAIT0(); }
        __syncthreads();
        if (kt + 2 < nk) gemmln_load_stage(sbase, A, Bt, K, bm, kt + 2, tid);

        const uint32_t ab = sbase + (uint32_t)(kt % 3) * LSTAGE;
        const uint32_t bb = ab + 8192;

        #pragma unroll
        for (int ks = 0; ks < 4; ks++) {
            const uint32_t aco = ((uint32_t)(ks * 32) + achunk) ^ mask;
            const uint32_t bco = ((uint32_t)(ks * 32) + bchunk) ^ mask;

            uint32_t afr[2][4], bfr[4][4];
            #pragma unroll
            for (int mt = 0; mt < 2; mt++) LDSM_X4(afr[mt], ab + arowb[mt] + aco);
            #pragma unroll
            for (int nh = 0; nh < 4; nh++) LDSM_X4(bfr[nh], bb + browb[nh] + bco);

            #pragma unroll
            for (int mt = 0; mt < 2; mt++)
                #pragma unroll
                for (int nt = 0; nt < 8; nt++)
                    mma_tf32(acc[mt][nt], afr[mt], &bfr[nt >> 1][(nt & 1) * 2]);
        }
    }
    __syncthreads();   // smem free for reductions now

    float* redS = (float*)smem;           // [64][4]
    float* redQ = (float*)smem + 256;     // [64][4]

    const int rl = lane >> 2;
    const int cl = (lane & 3) * 2;
    float sum[2][2] = {{0,0},{0,0}}, sq[2][2] = {{0,0},{0,0}};

    #pragma unroll
    for (int mt = 0; mt < 2; mt++) {
        const int rlo = bm + warpM * 32 + mt * 16 + rl;
        #pragma unroll
        for (int nt = 0; nt < 8; nt++) {
            const int col = warpN * 64 + nt * 8 + cl;
            const float2 bi = *(const float2*)&bias[col];
            const float2 r0 = *(const float2*)&res[(size_t)rlo * EE + col];
            const float2 r1 = *(const float2*)&res[(size_t)(rlo + 8) * EE + col];
            float v0 = acc[mt][nt][0] + bi.x + r0.x;
            float v1 = acc[mt][nt][1] + bi.y + r0.y;
            float v2 = acc[mt][nt][2] + bi.x + r1.x;
            float v3 = acc[mt][nt][3] + bi.y + r1.y;
            acc[mt][nt][0] = v0; acc[mt][nt][1] = v1;
            acc[mt][nt][2] = v2; acc[mt][nt][3] = v3;
            sum[mt][0] += v0 + v1;     sum[mt][1] += v2 + v3;
            sq[mt][0]  += v0*v0 + v1*v1; sq[mt][1] += v2*v2 + v3*v3;
        }
    }
    #pragma unroll
    for (int mt = 0; mt < 2; mt++)
        #pragma unroll
        for (int hh = 0; hh < 2; hh++) {
            sum[mt][hh] += __shfl_xor_sync(0xffffffffu, sum[mt][hh], 1);
            sum[mt][hh] += __shfl_xor_sync(0xffffffffu, sum[mt][hh], 2);
            sq[mt][hh]  += __shfl_xor_sync(0xffffffffu, sq[mt][hh], 1);
            sq[mt][hh]  += __shfl_xor_sync(0xffffffffu, sq[mt][hh], 2);
        }
    if ((lane & 3) == 0) {
        #pragma unroll
        for (int mt = 0; mt < 2; mt++) {
            int rloc = warpM * 32 + mt * 16 + rl;
            redS[rloc * 4 + warpN] = sum[mt][0];
            redQ[rloc * 4 + warpN] = sq[mt][0];
            redS[(rloc + 8) * 4 + warpN] = sum[mt][1];
            redQ[(rloc + 8) * 4 + warpN] = sq[mt][1];
        }
    }
    __syncthreads();

    #pragma unroll
    for (int mt = 0; mt < 2; mt++) {
        #pragma unroll
        for (int hh = 0; hh < 2; hh++) {
            const int rloc = warpM * 32 + mt * 16 + rl + hh * 8;
            float ts = redS[rloc * 4 + 0] + redS[rloc * 4 + 1]
                     + redS[rloc * 4 + 2] + redS[rloc * 4 + 3];
            float tq = redQ[rloc * 4 + 0] + redQ[rloc * 4 + 1]
                     + redQ[rloc * 4 + 2] + redQ[rloc * 4 + 3];
            const float mu = ts * (1.0f / (float)EE);
            const float var = tq * (1.0f / (float)EE) - mu * mu;
            const float inv = rsqrtf(var + EPS);
            const int row = bm + rloc;
            #pragma unroll
            for (int nt = 0; nt < 8; nt++) {
                const int col = warpN * 64 + nt * 8 + cl;
                const float2 gg = *(const float2*)&g[col];
                const float2 bb = *(const float2*)&beta[col];
                float v0 = acc[mt][nt][2 * hh + 0];
                float v1 = acc[mt][nt][2 * hh + 1];
                float2 o;
                o.x = (v0 - mu) * inv * gg.x + bb.x;
                o.y = (v1 - mu) * inv * gg.y + bb.y;
                if (roundOut) { o.x = tf32_rn(o.x); o.y = tf32_rn(o.y); }
                *(float2*)&out[(size_t)row * EE + col] = o;
            }
        }
    }
}

// ---------------------------------------------------------------------------
// Tensor-core flash attention (tf32 mma.sync) with cp.async KV pipeline.
// Block = (b,h) x 128-query tile; 8 warps x 16 rows. KV tiles of 64 keys,
// 3-stage cp.async. qkv values are pre-rounded to tf32 by the QKV GEMM.
// Softmax in log2 domain (Q scaled by scale*log2e; exp2f).
// qkv layout: [B,T,H,3,HD] -> (b*T+t)*768 + h*96 + s*32 + d
// ---------------------------------------------------------------------------
#define AST_K 8192                      // 64 keys x 128B (swizzled)
#define AST_V 10240                     // 64 keys x 40 floats
#define ASTAGE (AST_K + AST_V)          // 18432
#define APOFF (3 * ASTAGE)              // 55296: P buffers
#define PWARP (16 * 68 * 4)             // 4352 bytes per warp
#define ASMEM_TOTAL (APOFF + 8 * PWARP) // 90112

__device__ __forceinline__ void attn_load_kv(uint32_t sbase, const float* kv0,
                                             int kt, int tid) {
    uint32_t kbuf = sbase + (uint32_t)(kt % 3) * ASTAGE;
    uint32_t vbuf = kbuf + AST_K;
    const float* src0 = kv0 + (size_t)(kt * 64) * 768;
    #pragma unroll
    for (int i = 0; i < 2; i++) {
        int f = tid + i * 256;           // 0..511
        int j = f >> 3;                  // key 0..63
        int c = f & 7;                   // 16B chunk
        const float* s = src0 + (size_t)j * 768 + 32 + c * 4;   // K slot
        uint32_t koff = (uint32_t)(j * 128 + c * 16);
        CP_ASYNC16(kbuf + (koff ^ ((koff >> 3) & 0x70)), s);
        CP_ASYNC16(vbuf + (uint32_t)(j * 160 + c * 16), s + 32); // V slot
    }
    CP_COMMIT();
}

__global__ __launch_bounds__(256)
void attn_tc_kernel(const float* __restrict__ qkv, float* __restrict__ out) {
    extern __shared__ char smem[];
    uint32_t sbase = smem_u32(smem);

    const int tid = threadIdx.x;
    const int wid = tid >> 5;
    const int lane = tid & 31;
    const int qt = blockIdx.x;               // 0..15 (128 queries each)
    const int bh = blockIdx.y;               // 0..31
    const int h = bh & (HH - 1);
    const int b = bh >> 3;

    // scale * log2(e): softmax computed in log2 domain
    const float scale = 0.2550348612890183f;

    // --- Q fragments (A, m16k8 x 4 ksteps), pre-scaled + tf32 RN rounded ---
    uint32_t qfr[4][4];
    {
        const int r_lo = qt * 128 + wid * 16 + (lane >> 2);
        const size_t base_lo = (size_t)(b * TT + r_lo) * 768 + h * 96;
        const size_t base_hi = base_lo + 8 * 768;
        #pragma unroll
        for (int ks = 0; ks < 4; ks++) {
            int c0 = ks * 8 + (lane & 3);
            qfr[ks][0] = __float_as_uint(tf32_rn(qkv[base_lo + c0] * scale));
            qfr[ks][1] = __float_as_uint(tf32_rn(qkv[base_hi + c0] * scale));
            qfr[ks][2] = __float_as_uint(tf32_rn(qkv[base_lo + c0 + 4] * scale));
            qfr[ks][3] = __float_as_uint(tf32_rn(qkv[base_hi + c0 + 4] * scale));
        }
    }

    float ofr[4][4];
    #pragma unroll
    for (int nd = 0; nd < 4; nd++)
        #pragma unroll
        for (int r = 0; r < 4; r++) ofr[nd][r] = 0.0f;
    float m_lo = -INFINITY, m_hi = -INFINITY, l_lo = 0.0f, l_hi = 0.0f;

    // K ldmatrix addressing (B fragments over 64 keys)
    const uint32_t mask = (uint32_t)(lane & 7) << 4;
    const uint32_t krow = (uint32_t)((lane & 7) + ((lane >> 4) << 3)) * 128;
    const uint32_t kchunk = (uint32_t)((lane >> 3) & 1) * 16;

    // P buffers
    float* Pw = (float*)(smem + APOFF + wid * PWARP);
    const uint32_t pldsm = sbase + APOFF + (uint32_t)(wid * PWARP)
                         + (uint32_t)((lane & 15) * 272) + ((uint32_t)(lane >> 4) << 4);

    const float* kv0 = qkv + (size_t)(b * TT) * 768 + h * 96;

    attn_load_kv(sbase, kv0, 0, tid);
    attn_load_kv(sbase, kv0, 1, tid);

    const int nk = TT / 64;
    for (int kt = 0; kt < nk; kt++) {
        if (kt + 1 < nk) { CP_WAIT1(); } else { CP_WAIT0(); }
        __syncthreads();
        if (kt + 2 < nk) attn_load_kv(sbase, kv0, kt + 2, tid);

        const uint32_t kb = sbase + (uint32_t)(kt % 3) * ASTAGE;
        const uint32_t* Vsu = (const uint32_t*)(smem + (kt % 3) * ASTAGE + AST_K);

        // --- S = Q K^T ---
        float sfr[8][4];
        #pragma unroll
        for (int nt = 0; nt < 8; nt++)
            #pragma unroll
            for (int r = 0; r < 4; r++) sfr[nt][r] = 0.0f;

        #pragma unroll
        for (int ks = 0; ks < 4; ks++) {
            const uint32_t co = ((uint32_t)(ks * 32) + kchunk) ^ mask;
            uint32_t kfr[4][4];
            #pragma unroll
            for (int gI = 0; gI < 4; gI++)
                LDSM_X4(kfr[gI], kb + (uint32_t)(gI * 16 * 128) + krow + co);
            #pragma unroll
            for (int nt = 0; nt < 8; nt++)
                mma_tf32(sfr[nt], qfr[ks], &kfr[nt >> 1][(nt & 1) * 2]);
        }

        // --- online softmax (log2 domain) ---
        float mx_lo = sfr[0][0], mx_hi = sfr[0][2];
        #pragma unroll
        for (int nt = 0; nt < 8; nt++) {
            mx_lo = fmaxf(mx_lo, fmaxf(sfr[nt][0], sfr[nt][1]));
            mx_hi = fmaxf(mx_hi, fmaxf(sfr[nt][2], sfr[nt][3]));
        }
        mx_lo = fmaxf(mx_lo, __shfl_xor_sync(0xffffffffu, mx_lo, 1));
        mx_lo = fmaxf(mx_lo, __shfl_xor_sync(0xffffffffu, mx_lo, 2));
        mx_hi = fmaxf(mx_hi, __shfl_xor_sync(0xffffffffu, mx_hi, 1));
        mx_hi = fmaxf(mx_hi, __shfl_xor_sync(0xffffffffu, mx_hi, 2));

        const float nm_lo = fmaxf(m_lo, mx_lo);
        const float nm_hi = fmaxf(m_hi, mx_hi);
        const float corr_lo = exp2f(m_lo - nm_lo);   // 2^-inf = 0 first tile
        const float corr_hi = exp2f(m_hi - nm_hi);
        m_lo = nm_lo; m_hi = nm_hi;

        float ps_lo = 0.0f, ps_hi = 0.0f;
        {
            const int rl = (lane >> 2);
            const int cb = 2 * (lane & 3);
            float* prow_lo = Pw + rl * 68 + cb;
            float* prow_hi = Pw + (rl + 8) * 68 + cb;
            #pragma unroll
            for (int nt = 0; nt < 8; nt++) {
                float p0 = exp2f(sfr[nt][0] - m_lo);
                float p1 = exp2f(sfr[nt][1] - m_lo);
                float p2 = exp2f(sfr[nt][2] - m_hi);
                float p3 = exp2f(sfr[nt][3] - m_hi);
                ps_lo += p0 + p1;
                ps_hi += p2 + p3;
                float2 w0; w0.x = tf32_rn(p0); w0.y = tf32_rn(p1);
                float2 w1; w1.x = tf32_rn(p2); w1.y = tf32_rn(p3);
                *(float2*)(prow_lo + nt * 8) = w0;
                *(float2*)(prow_hi + nt * 8) = w1;
            }
        }
        l_lo = l_lo * corr_lo + ps_lo;
        l_hi = l_hi * corr_hi + ps_hi;
        #pragma unroll
        for (int nd = 0; nd < 4; nd++) {
            ofr[nd][0] *= corr_lo; ofr[nd][1] *= corr_lo;
            ofr[nd][2] *= corr_hi; ofr[nd][3] *= corr_hi;
        }
        __syncwarp();

        // --- O += P V : P via ldmatrix, V scalar (conflict-free pad 40) ---
        {
            const int rl = (lane >> 2);
            const int cl = (lane & 3);
            #pragma unroll
            for (int kk = 0; kk < 8; kk++) {
                uint32_t afr[4];
                LDSM_X4(afr, pldsm + (uint32_t)(kk * 32));
                #pragma unroll
                for (int nd = 0; nd < 4; nd++) {
                    uint32_t bfr[2];
                    bfr[0] = Vsu[(kk * 8 + cl) * 40 + nd * 8 + rl];
                    bfr[1] = Vsu[(kk * 8 + cl + 4) * 40 + nd * 8 + rl];
                    mma_tf32(ofr[nd], afr, bfr);
                }
            }
        }
        __syncwarp();
    }

    // final l reduction across quad + store (tf32-rounded for next GEMM)
    l_lo += __shfl_xor_sync(0xffffffffu, l_lo, 1);
    l_lo += __shfl_xor_sync(0xffffffffu, l_lo, 2);
    l_hi += __shfl_xor_sync(0xffffffffu, l_hi, 1);
    l_hi += __shfl_xor_sync(0xffffffffu, l_hi, 2);
    const float inv_lo = 1.0f / l_lo;
    const float inv_hi = 1.0f / l_hi;

    const int t_lo = qt * 128 + wid * 16 + (lane >> 2);
    const size_t ob_lo = (size_t)(b * TT + t_lo) * EE + h * HD + 2 * (lane & 3);
    const size_t ob_hi = ob_lo + 8 * EE;
    #pragma unroll
    for (int nd = 0; nd < 4; nd++) {
        float2 v0; v0.x = tf32_rn(ofr[nd][0] * inv_lo); v0.y = tf32_rn(ofr[nd][1] * inv_lo);
        float2 v1; v1.x = tf32_rn(ofr[nd][2] * inv_hi); v1.y = tf32_rn(ofr[nd][3] * inv_hi);
        *(float2*)&out[ob_lo + nd * 8] = v0;
        *(float2*)&out[ob_hi + nd * 8] = v1;
    }
}

// ---------------------------------------------------------------------------
// kernel_launch
// ---------------------------------------------------------------------------
extern "C" void kernel_launch(void* const* d_in, const int* in_sizes, int n_in,
                              void* d_out, int out_size) {
    const float* x     = (const float*)d_in[0];
    const float* qkv_w = (const float*)d_in[1];
    const float* qkv_b = (const float*)d_in[2];
    const float* out_w = (const float*)d_in[3];
    const float* out_b = (const float*)d_in[4];
    const float* ff1_w = (const float*)d_in[5];
    const float* ff1_b = (const float*)d_in[6];
    const float* ff2_w = (const float*)d_in[7];
    const float* ff2_b = (const float*)d_in[8];
    const float* ln1_g = (const float*)d_in[9];
    const float* ln1_b = (const float*)d_in[10];
    const float* ln2_g = (const float*)d_in[11];
    const float* ln2_b = (const float*)d_in[12];
    float* outp = (float*)d_out;

    float *gx, *gqkv, *gattn, *gffh, *wq, *wo, *w1, *w2;
    cudaGetSymbolAddress((void**)&gx,   g_x);
    cudaGetSymbolAddress((void**)&gqkv, g_qkv);
    cudaGetSymbolAddress((void**)&gattn,g_attn);
    cudaGetSymbolAddress((void**)&gffh, g_ffh);
    cudaGetSymbolAddress((void**)&wq,   g_qkvw_t);
    cudaGetSymbolAddress((void**)&wo,   g_outw_t);
    cudaGetSymbolAddress((void**)&w1,   g_ff1w_t);
    cudaGetSymbolAddress((void**)&w2,   g_ff2w_t);

    cudaFuncSetAttribute(gemm_tc_kernel, cudaFuncAttributeMaxDynamicSharedMemorySize, GSMEM_TOTAL);
    cudaFuncSetAttribute(gemm_ln_kernel, cudaFuncAttributeMaxDynamicSharedMemorySize, LSMEM_TOTAL);
    cudaFuncSetAttribute(attn_tc_kernel, cudaFuncAttributeMaxDynamicSharedMemorySize, ASMEM_TOTAL);

    const dim3 tthr(32, 8);
    transpose_kernel<<<dim3(24, 8, LL), tthr>>>(qkv_w, wq, EE, 3 * EE);
    transpose_kernel<<<dim3(8, 8, LL), tthr>>>(out_w, wo, EE, EE);
    transpose_kernel<<<dim3(32, 8, LL), tthr>>>(ff1_w, w1, EE, FEE * EE);
    transpose_kernel<<<dim3(8, 32, LL), tthr>>>(ff2_w, w2, FEE * EE, EE);

    pe_kernel<<<(MROWS * EE + 255) / 256, 256>>>(x, gx);

    for (int i = 0; i < LL; i++) {
        // qkv = x @ qkv_w + b    (8192 x 768, K=256)  -> tf32-rounded output
        gemm_tc_kernel<<<dim3(6, 64), 256, GSMEM_TOTAL>>>(
            gx, wq + (size_t)i * 3 * EE * EE, qkv_b + (size_t)i * 3 * EE,
            gqkv, 3 * EE, EE, 2);

        // tensor-core flash attention (output tf32-rounded)
        attn_tc_kernel<<<dim3(TT / 128, BB * HH), 256, ASMEM_TOTAL>>>(gqkv, gattn);

        // x = LN(x + attn @ out_w + out_b)    (fused; round for downstream GEMMs)
        gemm_ln_kernel<<<MROWS / 64, 256, LSMEM_TOTAL>>>(
            gattn, wo + (size_t)i * EE * EE, out_b + (size_t)i * EE,
            gx, ln1_g + (size_t)i * EE, ln1_b + (size_t)i * EE, gx, EE, 1);

        // h = relu(x @ ff1_w + b)  (8192 x 1024, K=256) -> relu + tf32-rounded
        gemm_tc_kernel<<<dim3(8, 64), 256, GSMEM_TOTAL>>>(
            gx, w1 + (size_t)i * FEE * EE * EE, ff1_b + (size_t)i * FEE * EE,
            gffh, FEE * EE, EE, 3);

        // x = LN(x + h @ ff2_w + ff2_b)       (fused; K=1024)
        float* dst = (i == LL - 1) ? outp : gx;
        gemm_ln_kernel<<<MROWS / 64, 256, LSMEM_TOTAL>>>(
            gffh, w2 + (size_t)i * FEE * EE * EE, ff2_b + (size_t)i * EE,
            gx, ln2_g + (size_t)i * EE, ln2_b + (size_t)i * EE, dst, FEE * EE,
            (i == LL - 1) ? 0 : 1);
    }
}